// round 3
// baseline (speedup 1.0000x reference)
#include <cuda_runtime.h>

// ODEINDLayer: B=256 independent systems. AtA is block-tridiagonal (100 blocks
// of 3x3, SPD). Solve exactly via block-Thomas (Schur-complement recurrence
// with symbolic Gram blocks). Compute fp64, store fp32. One thread per system.
//
// Gram blocks (ORDER=2), from Dt/Dt1 in the reference:
//   Dt  = [[1,h,h^2/2],[0,1,h],[-1,0,0],[0,-1,0],[0,-1,-h/2]]
//   Dt1 = [[-1,0,0],[0,-1,0],[1,-h,h^2/2],[0,1,-h],[0,1,-h/2]]
//   G = Dt^T Dt, H = Dt1^T Dt1, C = Dt^T Dt1.
// Diag block M_t = c_t c_t^T + [t<99] G(h_t) + [t>=1] H(h_{t-1}) + [t==0] diag(1,1,0)
// Off-diag block (t,t+1) = C(h_t).  rhs block = c_t*rhs_t + [t==0](iv0,iv1,0).

#define NSYS 256

__global__ __launch_bounds__(32)
void ode_thomas_kernel(const float* __restrict__ coeffs,
                       const float* __restrict__ rhs,
                       const float* __restrict__ iv_rhs,
                       const float* __restrict__ steps,
                       float* __restrict__ out)
{
    int b = blockIdx.x * blockDim.x + threadIdx.x;
    if (b >= NSYS) return;

    const float* C  = coeffs + b * 300;   // (100,3)
    const float* R  = rhs    + b * 100;   // (100,)
    const float* IV = iv_rhs + b * 2;     // (2,)
    const float* ST = steps  + b * 99;    // (99,)

    // Stored factorization state for the backward pass
    double inv[100][6];   // S_t^{-1} symmetric: 00,01,02,11,12,22
    double zs[100][3];    // eliminated rhs

    double pI00=0, pI01=0, pI02=0, pI11=0, pI12=0, pI22=0;
    double pz0=0, pz1=0, pz2=0;

    // ---------------- forward elimination ----------------
    for (int t = 0; t < 100; ++t) {
        double c0 = C[3*t+0], c1 = C[3*t+1], c2 = C[3*t+2];
        double rt = R[t];

        double M00 = c0*c0, M01 = c0*c1, M02 = c0*c2;
        double M11 = c1*c1, M12 = c1*c2, M22 = c2*c2;
        double b0 = c0*rt, b1 = c1*rt, b2 = c2*rt;

        if (t == 0) {
            M00 += 1.0; M11 += 1.0;
            b0 += (double)IV[0]; b1 += (double)IV[1];
        }
        if (t < 99) {               // G(h_t)
            double h = (double)ST[t], h2 = h*h;
            M00 += 2.0;        M01 += h;                    M02 += 0.5*h2;
            M11 += h2 + 3.0;   M12 += h*(0.5*h2 + 1.5);     M22 += h2*(0.25*h2 + 1.25);
        }
        if (t >= 1) {               // H(h_{t-1}) + Schur update via B = C(h_{t-1})
            double h = (double)ST[t-1], h2 = h*h;
            M00 += 2.0;        M01 -= h;                    M02 += 0.5*h2;
            M11 += h2 + 3.0;   M12 -= h*(0.5*h2 + 1.5);     M22 += h2*(0.25*h2 + 1.25);

            double B00=-2.0,     B01=h,       B02=-0.5*h2;
            double B10=-h,       B11=-3.0,    B12= 1.5*h;
            double B20=-0.5*h2,  B21=-1.5*h,  B22= 0.25*h2;

            // P = S_{t-1}^{-1} * B
            double P00 = pI00*B00 + pI01*B10 + pI02*B20;
            double P01 = pI00*B01 + pI01*B11 + pI02*B21;
            double P02 = pI00*B02 + pI01*B12 + pI02*B22;
            double P10 = pI01*B00 + pI11*B10 + pI12*B20;
            double P11 = pI01*B01 + pI11*B11 + pI12*B21;
            double P12 = pI01*B02 + pI11*B12 + pI12*B22;
            double P20 = pI02*B00 + pI12*B10 + pI22*B20;
            double P21 = pI02*B01 + pI12*B11 + pI22*B21;
            double P22 = pI02*B02 + pI12*B12 + pI22*B22;

            // M -= B^T P (= C^T S^{-1} C, symmetric)
            M00 -= B00*P00 + B10*P10 + B20*P20;
            M01 -= B00*P01 + B10*P11 + B20*P21;
            M02 -= B00*P02 + B10*P12 + B20*P22;
            M11 -= B01*P01 + B11*P11 + B21*P21;
            M12 -= B01*P02 + B11*P12 + B21*P22;
            M22 -= B02*P02 + B12*P12 + B22*P22;

            // rhs: b -= B^T (S_{t-1}^{-1} z_{t-1})
            double v0 = pI00*pz0 + pI01*pz1 + pI02*pz2;
            double v1 = pI01*pz0 + pI11*pz1 + pI12*pz2;
            double v2 = pI02*pz0 + pI12*pz1 + pI22*pz2;
            b0 -= B00*v0 + B10*v1 + B20*v2;
            b1 -= B01*v0 + B11*v1 + B21*v2;
            b2 -= B02*v0 + B12*v1 + B22*v2;
        }

        // invert 3x3 symmetric S_t via adjugate
        double A00 = M11*M22 - M12*M12;
        double A01 = M02*M12 - M01*M22;
        double A02 = M01*M12 - M02*M11;
        double A11 = M00*M22 - M02*M02;
        double A12 = M01*M02 - M00*M12;
        double A22 = M00*M11 - M01*M01;
        double det = M00*A00 + M01*A01 + M02*A02;
        double id  = 1.0 / det;
        pI00 = A00*id; pI01 = A01*id; pI02 = A02*id;
        pI11 = A11*id; pI12 = A12*id; pI22 = A22*id;
        pz0 = b0; pz1 = b1; pz2 = b2;

        inv[t][0]=pI00; inv[t][1]=pI01; inv[t][2]=pI02;
        inv[t][3]=pI11; inv[t][4]=pI12; inv[t][5]=pI22;
        zs[t][0]=b0; zs[t][1]=b1; zs[t][2]=b2;
    }

    // ---------------- back substitution ----------------
    float* u0 = out;
    float* u1 = out + 25600;
    float* u2 = out + 51200;

    double x0 = pI00*pz0 + pI01*pz1 + pI02*pz2;
    double x1 = pI01*pz0 + pI11*pz1 + pI12*pz2;
    double x2 = pI02*pz0 + pI12*pz1 + pI22*pz2;
    u0[b*100+99] = (float)x0; u1[b*100+99] = (float)x1; u2[b*100+99] = (float)x2;

    for (int t = 98; t >= 0; --t) {
        double h = (double)ST[t], h2 = h*h;
        double B00=-2.0,     B01=h,       B02=-0.5*h2;
        double B10=-h,       B11=-3.0,    B12= 1.5*h;
        double B20=-0.5*h2,  B21=-1.5*h,  B22= 0.25*h2;

        double r0 = zs[t][0] - (B00*x0 + B01*x1 + B02*x2);
        double r1 = zs[t][1] - (B10*x0 + B11*x1 + B12*x2);
        double r2 = zs[t][2] - (B20*x0 + B21*x1 + B22*x2);

        double I00=inv[t][0], I01=inv[t][1], I02=inv[t][2];
        double I11=inv[t][3], I12=inv[t][4], I22=inv[t][5];
        x0 = I00*r0 + I01*r1 + I02*r2;
        x1 = I01*r0 + I11*r1 + I12*r2;
        x2 = I02*r0 + I12*r1 + I22*r2;
        u0[b*100+t] = (float)x0; u1[b*100+t] = (float)x1; u2[b*100+t] = (float)x2;
    }

    // eps (zeros) and steps copy
    out[76800 + b] = 0.0f;
    float* stout = out + 77056;
    for (int t = 0; t < 99; ++t) stout[b*99 + t] = ST[t];
}

extern "C" void kernel_launch(void* const* d_in, const int* in_sizes, int n_in,
                              void* d_out, int out_size)
{
    (void)out_size;
    // Bind inputs by element count (robust to metadata ordering):
    // coeffs: 76800, rhs: 25600, iv_rhs: 512, steps: 25344.
    const float* coeffs = nullptr;
    const float* rhs    = nullptr;
    const float* iv_rhs = nullptr;
    const float* steps  = nullptr;
    for (int i = 0; i < n_in; ++i) {
        switch (in_sizes[i]) {
            case 76800: coeffs = (const float*)d_in[i]; break;
            case 25600: rhs    = (const float*)d_in[i]; break;
            case 512:   iv_rhs = (const float*)d_in[i]; break;
            case 25344: steps  = (const float*)d_in[i]; break;
            default: break;
        }
    }
    // Positional fallback (setup_inputs order) if size-binding missed.
    if (!coeffs && n_in > 0) coeffs = (const float*)d_in[0];
    if (!rhs    && n_in > 1) rhs    = (const float*)d_in[1];
    if (!iv_rhs && n_in > 2) iv_rhs = (const float*)d_in[2];
    if (!steps  && n_in > 3) steps  = (const float*)d_in[3];

    ode_thomas_kernel<<<8, 32>>>(coeffs, rhs, iv_rhs, steps, (float*)d_out);
}

// round 4
// speedup vs baseline: 6.1785x; 6.1785x over previous
#include <cuda_runtime.h>

// ODEINDLayer: 256 independent SPD block-tridiagonal systems (100 blocks of
// 3x3). Solved by BLOCK CYCLIC REDUCTION: 7 elimination levels + final 3x3
// solve + 7 back-substitution levels, one CTA per system, one thread per
// time-node, all state in shared memory, fp64 compute / fp32 store.
//
// Blocks (ORDER=2), derived from the reference's Dt/Dt1:
//   D_t = c_t c_t^T + [t<99] G(h_t) + [t>=1] H(h_{t-1}) + [t==0] diag(1,1,0)
//   U_t (coupling t -> t+1) = C(h_t) = [[-2,h,-h^2/2],[-h,-3,1.5h],[-h^2/2,-1.5h,h^2/4]]
//   L_{t+1} = U_t^T ; rhs_t = c_t*r_t + [t==0](iv0,iv1,0)
// CR preserves SPD + L=U^T symmetry at every level.

#define NSYS 256
#define NT   100

__global__ __launch_bounds__(128)
void ode_cr_kernel(const float* __restrict__ coeffs,
                   const float* __restrict__ rhs,
                   const float* __restrict__ iv_rhs,
                   const float* __restrict__ steps,
                   float* __restrict__ out)
{
    __shared__ double sD[NT][6];   // diag block, symmetric (00,01,02,11,12,22); holds inverse after elimination
    __shared__ double sU[NT][9];   // coupling t -> (t + stride), row-major
    __shared__ double sb[NT][3];   // rhs block
    __shared__ double sL[NT][9];   // snapshot of left coupling at elimination time
    __shared__ double sx[NT][3];   // solution

    const int sys = blockIdx.x;
    const int t   = threadIdx.x;

    const float* C  = coeffs + sys * 300;
    const float* R  = rhs    + sys * 100;
    const float* IV = iv_rhs + sys * 2;
    const float* ST = steps  + sys * 99;

    // ---------------- build ----------------
    if (t < NT) {
        double c0 = C[3*t], c1 = C[3*t+1], c2 = C[3*t+2];
        double rt = R[t];
        double D00=c0*c0, D01=c0*c1, D02=c0*c2, D11=c1*c1, D12=c1*c2, D22=c2*c2;
        double b0=c0*rt, b1=c1*rt, b2=c2*rt;
        if (t == 0) { D00 += 1.0; D11 += 1.0; b0 += (double)IV[0]; b1 += (double)IV[1]; }
        if (t < 99) {                       // G(h_t)
            double h = (double)ST[t], h2 = h*h;
            D00 += 2.0;      D01 += h;                D02 += 0.5*h2;
            D11 += h2+3.0;   D12 += h*(0.5*h2+1.5);   D22 += h2*(0.25*h2+1.25);
            sU[t][0]=-2.0;     sU[t][1]=h;       sU[t][2]=-0.5*h2;
            sU[t][3]=-h;       sU[t][4]=-3.0;    sU[t][5]=1.5*h;
            sU[t][6]=-0.5*h2;  sU[t][7]=-1.5*h;  sU[t][8]=0.25*h2;
        }
        if (t >= 1) {                       // H(h_{t-1})
            double h = (double)ST[t-1], h2 = h*h;
            D00 += 2.0;      D01 -= h;                D02 += 0.5*h2;
            D11 += h2+3.0;   D12 -= h*(0.5*h2+1.5);   D22 += h2*(0.25*h2+1.25);
        }
        sD[t][0]=D00; sD[t][1]=D01; sD[t][2]=D02; sD[t][3]=D11; sD[t][4]=D12; sD[t][5]=D22;
        sb[t][0]=b0;  sb[t][1]=b1;  sb[t][2]=b2;
    }
    __syncthreads();

    // ---------------- cyclic reduction: elimination ----------------
    #pragma unroll
    for (int s = 1; s <= 64; s <<= 1) {
        // Phase A: eliminated nodes (odd multiples of s) invert D in place,
        // snapshot left coupling for back-substitution.
        if (t < NT && (t % (2*s)) == s) {
            double M00=sD[t][0], M01=sD[t][1], M02=sD[t][2];
            double M11=sD[t][3], M12=sD[t][4], M22=sD[t][5];
            double A00 = M11*M22 - M12*M12;
            double A01 = M02*M12 - M01*M22;
            double A02 = M01*M12 - M02*M11;
            double A11 = M00*M22 - M02*M02;
            double A12 = M01*M02 - M00*M12;
            double A22 = M00*M11 - M01*M01;
            double id  = 1.0 / (M00*A00 + M01*A01 + M02*A02);
            sD[t][0]=A00*id; sD[t][1]=A01*id; sD[t][2]=A02*id;
            sD[t][3]=A11*id; sD[t][4]=A12*id; sD[t][5]=A22*id;
            #pragma unroll
            for (int k = 0; k < 9; ++k) sL[t][k] = sU[t-s][k];
        }
        __syncthreads();
        // Phase B: surviving nodes (multiples of 2s) absorb eliminated neighbors.
        if (t < NT && (t % (2*s)) == 0) {
            double D00=sD[t][0], D01=sD[t][1], D02=sD[t][2];
            double D11=sD[t][3], D12=sD[t][4], D22=sD[t][5];
            double b0=sb[t][0], b1=sb[t][1], b2=sb[t][2];

            if (t >= s) {  // left eliminated neighbor j = t-s; coupling U_j (j->t)
                int j = t - s;
                double I00=sD[j][0], I01=sD[j][1], I02=sD[j][2];
                double I11=sD[j][3], I12=sD[j][4], I22=sD[j][5];
                double U0=sU[j][0],U1=sU[j][1],U2=sU[j][2];
                double U3=sU[j][3],U4=sU[j][4],U5=sU[j][5];
                double U6=sU[j][6],U7=sU[j][7],U8=sU[j][8];
                // T = invD_j * U_j
                double T00=I00*U0+I01*U3+I02*U6, T01=I00*U1+I01*U4+I02*U7, T02=I00*U2+I01*U5+I02*U8;
                double T10=I01*U0+I11*U3+I12*U6, T11=I01*U1+I11*U4+I12*U7, T12=I01*U2+I11*U5+I12*U8;
                double T20=I02*U0+I12*U3+I22*U6, T21=I02*U1+I12*U4+I22*U7, T22=I02*U2+I12*U5+I22*U8;
                // D -= U_j^T T   (symmetric)
                D00 -= U0*T00 + U3*T10 + U6*T20;
                D01 -= U0*T01 + U3*T11 + U6*T21;
                D02 -= U0*T02 + U3*T12 + U6*T22;
                D11 -= U1*T01 + U4*T11 + U7*T21;
                D12 -= U1*T02 + U4*T12 + U7*T22;
                D22 -= U2*T02 + U5*T12 + U8*T22;
                // b -= U_j^T (invD_j b_j)
                double bj0=sb[j][0], bj1=sb[j][1], bj2=sb[j][2];
                double v0=I00*bj0+I01*bj1+I02*bj2;
                double v1=I01*bj0+I11*bj1+I12*bj2;
                double v2=I02*bj0+I12*bj1+I22*bj2;
                b0 -= U0*v0 + U3*v1 + U6*v2;
                b1 -= U1*v0 + U4*v1 + U7*v2;
                b2 -= U2*v0 + U5*v1 + U8*v2;
            }
            if (t + s <= 99) {  // right eliminated neighbor j = t+s; own coupling U_t (t->j)
                int j = t + s;
                double I00=sD[j][0], I01=sD[j][1], I02=sD[j][2];
                double I11=sD[j][3], I12=sD[j][4], I22=sD[j][5];
                double W0=sU[t][0],W1=sU[t][1],W2=sU[t][2];
                double W3=sU[t][3],W4=sU[t][4],W5=sU[t][5];
                double W6=sU[t][6],W7=sU[t][7],W8=sU[t][8];
                // P = U_t * invD_j
                double P00=W0*I00+W1*I01+W2*I02, P01=W0*I01+W1*I11+W2*I12, P02=W0*I02+W1*I12+W2*I22;
                double P10=W3*I00+W4*I01+W5*I02, P11=W3*I01+W4*I11+W5*I12, P12=W3*I02+W4*I12+W5*I22;
                double P20=W6*I00+W7*I01+W8*I02, P21=W6*I01+W7*I11+W8*I12, P22=W6*I02+W7*I12+W8*I22;
                // D -= P * U_t^T   (symmetric)
                D00 -= P00*W0 + P01*W1 + P02*W2;
                D01 -= P00*W3 + P01*W4 + P02*W5;
                D02 -= P00*W6 + P01*W7 + P02*W8;
                D11 -= P10*W3 + P11*W4 + P12*W5;
                D12 -= P10*W6 + P11*W7 + P12*W8;
                D22 -= P20*W6 + P21*W7 + P22*W8;
                // b -= P * b_j
                double bj0=sb[j][0], bj1=sb[j][1], bj2=sb[j][2];
                b0 -= P00*bj0 + P01*bj1 + P02*bj2;
                b1 -= P10*bj0 + P11*bj1 + P12*bj2;
                b2 -= P20*bj0 + P21*bj1 + P22*bj2;
                // new coupling t -> t+2s = -P * U_j  (exists iff t+2s <= 99)
                if (t + 2*s <= 99) {
                    double V0=sU[j][0],V1=sU[j][1],V2=sU[j][2];
                    double V3=sU[j][3],V4=sU[j][4],V5=sU[j][5];
                    double V6=sU[j][6],V7=sU[j][7],V8=sU[j][8];
                    sU[t][0] = -(P00*V0 + P01*V3 + P02*V6);
                    sU[t][1] = -(P00*V1 + P01*V4 + P02*V7);
                    sU[t][2] = -(P00*V2 + P01*V5 + P02*V8);
                    sU[t][3] = -(P10*V0 + P11*V3 + P12*V6);
                    sU[t][4] = -(P10*V1 + P11*V4 + P12*V7);
                    sU[t][5] = -(P10*V2 + P11*V5 + P12*V8);
                    sU[t][6] = -(P20*V0 + P21*V3 + P22*V6);
                    sU[t][7] = -(P20*V1 + P21*V4 + P22*V7);
                    sU[t][8] = -(P20*V2 + P21*V5 + P22*V8);
                }
            }
            sD[t][0]=D00; sD[t][1]=D01; sD[t][2]=D02; sD[t][3]=D11; sD[t][4]=D12; sD[t][5]=D22;
            sb[t][0]=b0;  sb[t][1]=b1;  sb[t][2]=b2;
        }
        __syncthreads();
    }

    // ---------------- root solve (node 0) ----------------
    if (t == 0) {
        double M00=sD[0][0], M01=sD[0][1], M02=sD[0][2];
        double M11=sD[0][3], M12=sD[0][4], M22=sD[0][5];
        double A00 = M11*M22 - M12*M12;
        double A01 = M02*M12 - M01*M22;
        double A02 = M01*M12 - M02*M11;
        double A11 = M00*M22 - M02*M02;
        double A12 = M01*M02 - M00*M12;
        double A22 = M00*M11 - M01*M01;
        double id  = 1.0 / (M00*A00 + M01*A01 + M02*A02);
        double b0=sb[0][0], b1=sb[0][1], b2=sb[0][2];
        sx[0][0] = (A00*b0 + A01*b1 + A02*b2) * id;
        sx[0][1] = (A01*b0 + A11*b1 + A12*b2) * id;
        sx[0][2] = (A02*b0 + A12*b1 + A22*b2) * id;
    }
    __syncthreads();

    // ---------------- back substitution ----------------
    #pragma unroll
    for (int s = 64; s >= 1; s >>= 1) {
        if (t < NT && (t % (2*s)) == s) {
            double r0=sb[t][0], r1=sb[t][1], r2=sb[t][2];
            // left term: L_t = Lsnap^T, x_{t-s}
            double xl0=sx[t-s][0], xl1=sx[t-s][1], xl2=sx[t-s][2];
            r0 -= sL[t][0]*xl0 + sL[t][3]*xl1 + sL[t][6]*xl2;
            r1 -= sL[t][1]*xl0 + sL[t][4]*xl1 + sL[t][7]*xl2;
            r2 -= sL[t][2]*xl0 + sL[t][5]*xl1 + sL[t][8]*xl2;
            if (t + s <= 99) {
                double xr0=sx[t+s][0], xr1=sx[t+s][1], xr2=sx[t+s][2];
                r0 -= sU[t][0]*xr0 + sU[t][1]*xr1 + sU[t][2]*xr2;
                r1 -= sU[t][3]*xr0 + sU[t][4]*xr1 + sU[t][5]*xr2;
                r2 -= sU[t][6]*xr0 + sU[t][7]*xr1 + sU[t][8]*xr2;
            }
            double I00=sD[t][0], I01=sD[t][1], I02=sD[t][2];
            double I11=sD[t][3], I12=sD[t][4], I22=sD[t][5];
            sx[t][0] = I00*r0 + I01*r1 + I02*r2;
            sx[t][1] = I01*r0 + I11*r1 + I12*r2;
            sx[t][2] = I02*r0 + I12*r1 + I22*r2;
        }
        __syncthreads();
    }

    // ---------------- outputs ----------------
    if (t < NT) {
        out[          sys*100 + t] = (float)sx[t][0];
        out[25600 +   sys*100 + t] = (float)sx[t][1];
        out[51200 +   sys*100 + t] = (float)sx[t][2];
    }
    if (t == 0) out[76800 + sys] = 0.0f;
    if (t < 99) out[77056 + sys*99 + t] = ST[t];
}

extern "C" void kernel_launch(void* const* d_in, const int* in_sizes, int n_in,
                              void* d_out, int out_size)
{
    (void)out_size;
    // Bind inputs by element count:
    // coeffs: 76800, rhs: 25600, iv_rhs: 512, steps: 25344.
    const float* coeffs = nullptr;
    const float* rhs    = nullptr;
    const float* iv_rhs = nullptr;
    const float* steps  = nullptr;
    for (int i = 0; i < n_in; ++i) {
        switch (in_sizes[i]) {
            case 76800: coeffs = (const float*)d_in[i]; break;
            case 25600: rhs    = (const float*)d_in[i]; break;
            case 512:   iv_rhs = (const float*)d_in[i]; break;
            case 25344: steps  = (const float*)d_in[i]; break;
            default: break;
        }
    }
    if (!coeffs && n_in > 0) coeffs = (const float*)d_in[0];
    if (!rhs    && n_in > 1) rhs    = (const float*)d_in[1];
    if (!iv_rhs && n_in > 2) iv_rhs = (const float*)d_in[2];
    if (!steps  && n_in > 3) steps  = (const float*)d_in[3];

    ode_cr_kernel<<<NSYS, 128>>>(coeffs, rhs, iv_rhs, steps, (float*)d_out);
}

// round 5
// speedup vs baseline: 19.8372x; 3.2107x over previous
#include <cuda_runtime.h>

// ODEINDLayer: 256 independent SPD block-tridiagonal systems (100 blocks of
// 3x3). Mixed-precision: fp32 block cyclic reduction (factor + solve) with
// fp64 iterative refinement against the exact fp64 matrix. One CTA per
// system, one thread per time-node.
//
// Blocks (ORDER=2), from the reference's Dt/Dt1:
//   D_t = c_t c_t^T + [t<99] G(h_t) + [t>=1] H(h_{t-1}) + [t==0] diag(1,1,0)
//   U_t = C(h_t) = [[-2,h,-h^2/2],[-h,-3,1.5h],[-h^2/2,-1.5h,h^2/4]]
//   L_{t+1} = U_t^T ; rhs_t = c_t*r_t + [t==0](iv0,iv1,0)

#define NSYS 256
#define NT   100
#define NREFINE 2

__device__ __forceinline__ float frcp(float x) {
    float r; asm("rcp.approx.f32 %0, %1;" : "=f"(r) : "f"(x)); return r;
}

__global__ __launch_bounds__(128)
void ode_cr_mixed_kernel(const float* __restrict__ coeffs,
                         const float* __restrict__ rhs,
                         const float* __restrict__ iv_rhs,
                         const float* __restrict__ steps,
                         float* __restrict__ out)
{
    __shared__ float  fD[NT][6];   // fp32 diag; becomes inverse for eliminated nodes and root
    __shared__ float  fU[NT][9];   // coupling t -> t+stride (live during factor; preserved for eliminated nodes)
    __shared__ float  fL[NT][9];   // snapshot of left coupling U_{t-s} at elimination time
    __shared__ float  fb[NT][3];   // rhs workspace (fp32)
    __shared__ float  fx[NT][3];   // fp32 solve result
    __shared__ double dx[NT][3];   // accumulated fp64 solution

    const int sys = blockIdx.x;
    const int t   = threadIdx.x;

    const float* C  = coeffs + sys * 300;
    const float* R  = rhs    + sys * 100;
    const float* IV = iv_rhs + sys * 2;
    const float* ST = steps  + sys * 99;

    // -------- fp64 build (register-cached for residuals) --------
    double D0=0,D1=0,D2=0,D3=0,D4=0,D5=0, b0=0,b1=0,b2=0;
    double U[9] = {0,0,0,0,0,0,0,0,0};
    double L[9] = {0,0,0,0,0,0,0,0,0};
    float st_local = 0.0f;

    if (t < NT) {
        double c0 = C[3*t], c1 = C[3*t+1], c2 = C[3*t+2];
        double rt = R[t];
        D0=c0*c0; D1=c0*c1; D2=c0*c2; D3=c1*c1; D4=c1*c2; D5=c2*c2;
        b0=c0*rt; b1=c1*rt; b2=c2*rt;
        if (t == 0) { D0 += 1.0; D3 += 1.0; b0 += (double)IV[0]; b1 += (double)IV[1]; }
        if (t < 99) {
            st_local = ST[t];
            double h = (double)st_local, h2 = h*h;
            D0 += 2.0;      D1 += h;               D2 += 0.5*h2;
            D3 += h2+3.0;   D4 += h*(0.5*h2+1.5);  D5 += h2*(0.25*h2+1.25);
            U[0]=-2.0;    U[1]=h;      U[2]=-0.5*h2;
            U[3]=-h;      U[4]=-3.0;   U[5]=1.5*h;
            U[6]=-0.5*h2; U[7]=-1.5*h; U[8]=0.25*h2;
        }
        if (t >= 1) {
            double g = (double)ST[t-1], g2 = g*g;
            D0 += 2.0;      D1 -= g;               D2 += 0.5*g2;
            D3 += g2+3.0;   D4 -= g*(0.5*g2+1.5);  D5 += g2*(0.25*g2+1.25);
            L[0]=-2.0;    L[1]=g;      L[2]=-0.5*g2;   // = U_{t-1} (applied transposed)
            L[3]=-g;      L[4]=-3.0;   L[5]=1.5*g;
            L[6]=-0.5*g2; L[7]=-1.5*g; L[8]=0.25*g2;
        }
        fD[t][0]=(float)D0; fD[t][1]=(float)D1; fD[t][2]=(float)D2;
        fD[t][3]=(float)D3; fD[t][4]=(float)D4; fD[t][5]=(float)D5;
        #pragma unroll
        for (int k = 0; k < 9; ++k) fU[t][k] = (float)U[k];
        fb[t][0]=(float)b0; fb[t][1]=(float)b1; fb[t][2]=(float)b2;
    }
    __syncthreads();

    // -------- fp32 CR: factorization + first solve --------
    #pragma unroll
    for (int s = 1; s <= 64; s <<= 1) {
        // Phase A: eliminated nodes invert D in place; snapshot left coupling.
        if (t < NT && (t % (2*s)) == s) {
            float M00=fD[t][0], M01=fD[t][1], M02=fD[t][2];
            float M11=fD[t][3], M12=fD[t][4], M22=fD[t][5];
            float A00 = M11*M22 - M12*M12;
            float A01 = M02*M12 - M01*M22;
            float A02 = M01*M12 - M02*M11;
            float A11 = M00*M22 - M02*M02;
            float A12 = M01*M02 - M00*M12;
            float A22 = M00*M11 - M01*M01;
            float id  = frcp(M00*A00 + M01*A01 + M02*A02);
            fD[t][0]=A00*id; fD[t][1]=A01*id; fD[t][2]=A02*id;
            fD[t][3]=A11*id; fD[t][4]=A12*id; fD[t][5]=A22*id;
            #pragma unroll
            for (int k = 0; k < 9; ++k) fL[t][k] = fU[t-s][k];
        }
        __syncthreads();
        // Phase B: survivors absorb eliminated neighbors.
        if (t < NT && (t % (2*s)) == 0) {
            float E00=fD[t][0], E01=fD[t][1], E02=fD[t][2];
            float E11=fD[t][3], E12=fD[t][4], E22=fD[t][5];
            float g0=fb[t][0], g1=fb[t][1], g2=fb[t][2];

            if (t >= s) {
                int j = t - s;
                float I00=fD[j][0], I01=fD[j][1], I02=fD[j][2];
                float I11=fD[j][3], I12=fD[j][4], I22=fD[j][5];
                float W0=fU[j][0],W1=fU[j][1],W2=fU[j][2];
                float W3=fU[j][3],W4=fU[j][4],W5=fU[j][5];
                float W6=fU[j][6],W7=fU[j][7],W8=fU[j][8];
                float T00=I00*W0+I01*W3+I02*W6, T01=I00*W1+I01*W4+I02*W7, T02=I00*W2+I01*W5+I02*W8;
                float T10=I01*W0+I11*W3+I12*W6, T11=I01*W1+I11*W4+I12*W7, T12=I01*W2+I11*W5+I12*W8;
                float T20=I02*W0+I12*W3+I22*W6, T21=I02*W1+I12*W4+I22*W7, T22=I02*W2+I12*W5+I22*W8;
                E00 -= W0*T00 + W3*T10 + W6*T20;
                E01 -= W0*T01 + W3*T11 + W6*T21;
                E02 -= W0*T02 + W3*T12 + W6*T22;
                E11 -= W1*T01 + W4*T11 + W7*T21;
                E12 -= W1*T02 + W4*T12 + W7*T22;
                E22 -= W2*T02 + W5*T12 + W8*T22;
                float bj0=fb[j][0], bj1=fb[j][1], bj2=fb[j][2];
                float v0=I00*bj0+I01*bj1+I02*bj2;
                float v1=I01*bj0+I11*bj1+I12*bj2;
                float v2=I02*bj0+I12*bj1+I22*bj2;
                g0 -= W0*v0 + W3*v1 + W6*v2;
                g1 -= W1*v0 + W4*v1 + W7*v2;
                g2 -= W2*v0 + W5*v1 + W8*v2;
            }
            if (t + s <= 99) {
                int j = t + s;
                float I00=fD[j][0], I01=fD[j][1], I02=fD[j][2];
                float I11=fD[j][3], I12=fD[j][4], I22=fD[j][5];
                float W0=fU[t][0],W1=fU[t][1],W2=fU[t][2];
                float W3=fU[t][3],W4=fU[t][4],W5=fU[t][5];
                float W6=fU[t][6],W7=fU[t][7],W8=fU[t][8];
                float P00=W0*I00+W1*I01+W2*I02, P01=W0*I01+W1*I11+W2*I12, P02=W0*I02+W1*I12+W2*I22;
                float P10=W3*I00+W4*I01+W5*I02, P11=W3*I01+W4*I11+W5*I12, P12=W3*I02+W4*I12+W5*I22;
                float P20=W6*I00+W7*I01+W8*I02, P21=W6*I01+W7*I11+W8*I12, P22=W6*I02+W7*I12+W8*I22;
                E00 -= P00*W0 + P01*W1 + P02*W2;
                E01 -= P00*W3 + P01*W4 + P02*W5;
                E02 -= P00*W6 + P01*W7 + P02*W8;
                E11 -= P10*W3 + P11*W4 + P12*W5;
                E12 -= P10*W6 + P11*W7 + P12*W8;
                E22 -= P20*W6 + P21*W7 + P22*W8;
                float bj0=fb[j][0], bj1=fb[j][1], bj2=fb[j][2];
                g0 -= P00*bj0 + P01*bj1 + P02*bj2;
                g1 -= P10*bj0 + P11*bj1 + P12*bj2;
                g2 -= P20*bj0 + P21*bj1 + P22*bj2;
                if (t + 2*s <= 99) {
                    float V0=fU[j][0],V1=fU[j][1],V2=fU[j][2];
                    float V3=fU[j][3],V4=fU[j][4],V5=fU[j][5];
                    float V6=fU[j][6],V7=fU[j][7],V8=fU[j][8];
                    fU[t][0] = -(P00*V0 + P01*V3 + P02*V6);
                    fU[t][1] = -(P00*V1 + P01*V4 + P02*V7);
                    fU[t][2] = -(P00*V2 + P01*V5 + P02*V8);
                    fU[t][3] = -(P10*V0 + P11*V3 + P12*V6);
                    fU[t][4] = -(P10*V1 + P11*V4 + P12*V7);
                    fU[t][5] = -(P10*V2 + P11*V5 + P12*V8);
                    fU[t][6] = -(P20*V0 + P21*V3 + P22*V6);
                    fU[t][7] = -(P20*V1 + P21*V4 + P22*V7);
                    fU[t][8] = -(P20*V2 + P21*V5 + P22*V8);
                }
            }
            fD[t][0]=E00; fD[t][1]=E01; fD[t][2]=E02; fD[t][3]=E11; fD[t][4]=E12; fD[t][5]=E22;
            fb[t][0]=g0;  fb[t][1]=g1;  fb[t][2]=g2;
        }
        __syncthreads();
    }

    // Root: invert D0 in place (kept for refinement solves), solve x0.
    if (t == 0) {
        float M00=fD[0][0], M01=fD[0][1], M02=fD[0][2];
        float M11=fD[0][3], M12=fD[0][4], M22=fD[0][5];
        float A00 = M11*M22 - M12*M12;
        float A01 = M02*M12 - M01*M22;
        float A02 = M01*M12 - M02*M11;
        float A11 = M00*M22 - M02*M02;
        float A12 = M01*M02 - M00*M12;
        float A22 = M00*M11 - M01*M01;
        float id  = frcp(M00*A00 + M01*A01 + M02*A02);
        fD[0][0]=A00*id; fD[0][1]=A01*id; fD[0][2]=A02*id;
        fD[0][3]=A11*id; fD[0][4]=A12*id; fD[0][5]=A22*id;
        float g0=fb[0][0], g1=fb[0][1], g2=fb[0][2];
        fx[0][0] = fD[0][0]*g0 + fD[0][1]*g1 + fD[0][2]*g2;
        fx[0][1] = fD[0][1]*g0 + fD[0][3]*g1 + fD[0][4]*g2;
        fx[0][2] = fD[0][2]*g0 + fD[0][4]*g1 + fD[0][5]*g2;
    }
    __syncthreads();

    // Back substitution (fp32).
    #pragma unroll
    for (int s = 64; s >= 1; s >>= 1) {
        if (t < NT && (t % (2*s)) == s) {
            float r0=fb[t][0], r1=fb[t][1], r2=fb[t][2];
            float xl0=fx[t-s][0], xl1=fx[t-s][1], xl2=fx[t-s][2];
            r0 -= fL[t][0]*xl0 + fL[t][3]*xl1 + fL[t][6]*xl2;
            r1 -= fL[t][1]*xl0 + fL[t][4]*xl1 + fL[t][7]*xl2;
            r2 -= fL[t][2]*xl0 + fL[t][5]*xl1 + fL[t][8]*xl2;
            if (t + s <= 99) {
                float xr0=fx[t+s][0], xr1=fx[t+s][1], xr2=fx[t+s][2];
                r0 -= fU[t][0]*xr0 + fU[t][1]*xr1 + fU[t][2]*xr2;
                r1 -= fU[t][3]*xr0 + fU[t][4]*xr1 + fU[t][5]*xr2;
                r2 -= fU[t][6]*xr0 + fU[t][7]*xr1 + fU[t][8]*xr2;
            }
            float I00=fD[t][0], I01=fD[t][1], I02=fD[t][2];
            float I11=fD[t][3], I12=fD[t][4], I22=fD[t][5];
            fx[t][0] = I00*r0 + I01*r1 + I02*r2;
            fx[t][1] = I01*r0 + I11*r1 + I12*r2;
            fx[t][2] = I02*r0 + I12*r1 + I22*r2;
        }
        __syncthreads();
    }
    if (t < NT) { dx[t][0]=fx[t][0]; dx[t][1]=fx[t][1]; dx[t][2]=fx[t][2]; }
    __syncthreads();

    // -------- iterative refinement --------
    for (int it = 0; it < NREFINE; ++it) {
        // fp64 residual against the exact fp64 matrix (register-cached).
        if (t < NT) {
            double x0=dx[t][0], x1=dx[t][1], x2=dx[t][2];
            double r0 = b0 - (D0*x0 + D1*x1 + D2*x2);
            double r1 = b1 - (D1*x0 + D3*x1 + D4*x2);
            double r2 = b2 - (D2*x0 + D4*x1 + D5*x2);
            if (t < 99) {
                double y0=dx[t+1][0], y1=dx[t+1][1], y2=dx[t+1][2];
                r0 -= U[0]*y0 + U[1]*y1 + U[2]*y2;
                r1 -= U[3]*y0 + U[4]*y1 + U[5]*y2;
                r2 -= U[6]*y0 + U[7]*y1 + U[8]*y2;
            }
            if (t >= 1) {   // L_t = U_{t-1}^T
                double y0=dx[t-1][0], y1=dx[t-1][1], y2=dx[t-1][2];
                r0 -= L[0]*y0 + L[3]*y1 + L[6]*y2;
                r1 -= L[1]*y0 + L[4]*y1 + L[7]*y2;
                r2 -= L[2]*y0 + L[5]*y1 + L[8]*y2;
            }
            fb[t][0]=(float)r0; fb[t][1]=(float)r1; fb[t][2]=(float)r2;
        }
        __syncthreads();

        // fp32 forward rhs-elimination using stored factors.
        #pragma unroll
        for (int s = 1; s <= 64; s <<= 1) {
            if (t < NT && (t % (2*s)) == 0) {
                float g0=fb[t][0], g1=fb[t][1], g2=fb[t][2];
                if (t >= s) {   // left eliminated j: g -= U_j^T (invD_j b_j)
                    int j = t - s;
                    float bj0=fb[j][0], bj1=fb[j][1], bj2=fb[j][2];
                    float v0=fD[j][0]*bj0+fD[j][1]*bj1+fD[j][2]*bj2;
                    float v1=fD[j][1]*bj0+fD[j][3]*bj1+fD[j][4]*bj2;
                    float v2=fD[j][2]*bj0+fD[j][4]*bj1+fD[j][5]*bj2;
                    g0 -= fU[j][0]*v0 + fU[j][3]*v1 + fU[j][6]*v2;
                    g1 -= fU[j][1]*v0 + fU[j][4]*v1 + fU[j][7]*v2;
                    g2 -= fU[j][2]*v0 + fU[j][5]*v1 + fU[j][8]*v2;
                }
                if (t + s <= 99) {  // right eliminated j: g -= U_t (invD_j b_j), U_t == fL[j]
                    int j = t + s;
                    float bj0=fb[j][0], bj1=fb[j][1], bj2=fb[j][2];
                    float v0=fD[j][0]*bj0+fD[j][1]*bj1+fD[j][2]*bj2;
                    float v1=fD[j][1]*bj0+fD[j][3]*bj1+fD[j][4]*bj2;
                    float v2=fD[j][2]*bj0+fD[j][4]*bj1+fD[j][5]*bj2;
                    g0 -= fL[j][0]*v0 + fL[j][1]*v1 + fL[j][2]*v2;
                    g1 -= fL[j][3]*v0 + fL[j][4]*v1 + fL[j][5]*v2;
                    g2 -= fL[j][6]*v0 + fL[j][7]*v1 + fL[j][8]*v2;
                }
                fb[t][0]=g0; fb[t][1]=g1; fb[t][2]=g2;
            }
            __syncthreads();
        }
        // Root solve (fD[0] holds the inverse).
        if (t == 0) {
            float g0=fb[0][0], g1=fb[0][1], g2=fb[0][2];
            fx[0][0] = fD[0][0]*g0 + fD[0][1]*g1 + fD[0][2]*g2;
            fx[0][1] = fD[0][1]*g0 + fD[0][3]*g1 + fD[0][4]*g2;
            fx[0][2] = fD[0][2]*g0 + fD[0][4]*g1 + fD[0][5]*g2;
        }
        __syncthreads();
        // Back substitution.
        #pragma unroll
        for (int s = 64; s >= 1; s >>= 1) {
            if (t < NT && (t % (2*s)) == s) {
                float r0=fb[t][0], r1=fb[t][1], r2=fb[t][2];
                float xl0=fx[t-s][0], xl1=fx[t-s][1], xl2=fx[t-s][2];
                r0 -= fL[t][0]*xl0 + fL[t][3]*xl1 + fL[t][6]*xl2;
                r1 -= fL[t][1]*xl0 + fL[t][4]*xl1 + fL[t][7]*xl2;
                r2 -= fL[t][2]*xl0 + fL[t][5]*xl1 + fL[t][8]*xl2;
                if (t + s <= 99) {
                    float xr0=fx[t+s][0], xr1=fx[t+s][1], xr2=fx[t+s][2];
                    r0 -= fU[t][0]*xr0 + fU[t][1]*xr1 + fU[t][2]*xr2;
                    r1 -= fU[t][3]*xr0 + fU[t][4]*xr1 + fU[t][5]*xr2;
                    r2 -= fU[t][6]*xr0 + fU[t][7]*xr1 + fU[t][8]*xr2;
                }
                float I00=fD[t][0], I01=fD[t][1], I02=fD[t][2];
                float I11=fD[t][3], I12=fD[t][4], I22=fD[t][5];
                fx[t][0] = I00*r0 + I01*r1 + I02*r2;
                fx[t][1] = I01*r0 + I11*r1 + I12*r2;
                fx[t][2] = I02*r0 + I12*r1 + I22*r2;
            }
            __syncthreads();
        }
        if (t < NT) {
            dx[t][0] += (double)fx[t][0];
            dx[t][1] += (double)fx[t][1];
            dx[t][2] += (double)fx[t][2];
        }
        __syncthreads();
    }

    // -------- outputs --------
    if (t < NT) {
        out[        sys*100 + t] = (float)dx[t][0];
        out[25600 + sys*100 + t] = (float)dx[t][1];
        out[51200 + sys*100 + t] = (float)dx[t][2];
    }
    if (t == 0) out[76800 + sys] = 0.0f;
    if (t < 99) out[77056 + sys*99 + t] = st_local;
}

extern "C" void kernel_launch(void* const* d_in, const int* in_sizes, int n_in,
                              void* d_out, int out_size)
{
    (void)out_size;
    const float* coeffs = nullptr;
    const float* rhs    = nullptr;
    const float* iv_rhs = nullptr;
    const float* steps  = nullptr;
    for (int i = 0; i < n_in; ++i) {
        switch (in_sizes[i]) {
            case 76800: coeffs = (const float*)d_in[i]; break;
            case 25600: rhs    = (const float*)d_in[i]; break;
            case 512:   iv_rhs = (const float*)d_in[i]; break;
            case 25344: steps  = (const float*)d_in[i]; break;
            default: break;
        }
    }
    if (!coeffs && n_in > 0) coeffs = (const float*)d_in[0];
    if (!rhs    && n_in > 1) rhs    = (const float*)d_in[1];
    if (!iv_rhs && n_in > 2) iv_rhs = (const float*)d_in[2];
    if (!steps  && n_in > 3) steps  = (const float*)d_in[3];

    ode_cr_mixed_kernel<<<NSYS, 128>>>(coeffs, rhs, iv_rhs, steps, (float*)d_out);
}

// round 6
// speedup vs baseline: 24.4759x; 1.2338x over previous
#include <cuda_runtime.h>

// ODEINDLayer: 256 independent SPD block-tridiagonal systems (100 blocks of
// 3x3). fp32 block cyclic reduction with fused elimination phases (one
// barrier per level) + ONE fp64 iterative-refinement step against the exact
// fp64 matrix held in registers. One CTA per system, one thread per node.

#define NSYS 256
#define NT   100

__device__ __forceinline__ float frcp(float x) {
    float r; asm("rcp.approx.f32 %0, %1;" : "=f"(r) : "f"(x)); return r;
}

// Invert symmetric 3x3 (packed 00,01,02,11,12,22) via adjugate.
__device__ __forceinline__ void inv3_sym(const float M[6], float I[6]) {
    float A00 = M[3]*M[5] - M[4]*M[4];
    float A01 = M[2]*M[4] - M[1]*M[5];
    float A02 = M[1]*M[4] - M[2]*M[3];
    float A11 = M[0]*M[5] - M[2]*M[2];
    float A12 = M[1]*M[2] - M[0]*M[4];
    float A22 = M[0]*M[3] - M[1]*M[1];
    float id  = frcp(M[0]*A00 + M[1]*A01 + M[2]*A02);
    I[0]=A00*id; I[1]=A01*id; I[2]=A02*id; I[3]=A11*id; I[4]=A12*id; I[5]=A22*id;
}

__global__ __launch_bounds__(128)
void ode_cr_fused_kernel(const float* __restrict__ coeffs,
                         const float* __restrict__ rhs,
                         const float* __restrict__ iv_rhs,
                         const float* __restrict__ steps,
                         float* __restrict__ out)
{
    __shared__ float fD [NT][6];   // raw diag (updated by survivors)
    __shared__ float fDi[NT][6];   // inverse diag (eliminated nodes + root)
    __shared__ float fU [NT][9];   // coupling t -> t+stride (frozen at elimination)
    __shared__ float fL [NT][9];   // snapshot: coupling (t-s) -> t at elimination level
    __shared__ float fb [NT][3];   // rhs workspace
    __shared__ float fx [NT][3];   // solution workspace

    const int sys = blockIdx.x;
    const int t   = threadIdx.x;

    const float* C  = coeffs + sys * 300;
    const float* R  = rhs    + sys * 100;
    const float* IV = iv_rhs + sys * 2;
    const float* ST = steps  + sys * 99;

    // -------- fp64 build, register-cached for the residual --------
    double D0=0,D1=0,D2=0,D3=0,D4=0,D5=0, b0=0,b1=0,b2=0;
    double U[9] = {0,0,0,0,0,0,0,0,0};
    double L[9] = {0,0,0,0,0,0,0,0,0};
    float st_local = 0.0f;

    if (t < NT) {
        double c0 = C[3*t], c1 = C[3*t+1], c2 = C[3*t+2];
        double rt = R[t];
        D0=c0*c0; D1=c0*c1; D2=c0*c2; D3=c1*c1; D4=c1*c2; D5=c2*c2;
        b0=c0*rt; b1=c1*rt; b2=c2*rt;
        if (t == 0) { D0 += 1.0; D3 += 1.0; b0 += (double)IV[0]; b1 += (double)IV[1]; }
        if (t < 99) {
            st_local = ST[t];
            double h = (double)st_local, h2 = h*h;
            D0 += 2.0;      D1 += h;               D2 += 0.5*h2;
            D3 += h2+3.0;   D4 += h*(0.5*h2+1.5);  D5 += h2*(0.25*h2+1.25);
            U[0]=-2.0;    U[1]=h;      U[2]=-0.5*h2;
            U[3]=-h;      U[4]=-3.0;   U[5]=1.5*h;
            U[6]=-0.5*h2; U[7]=-1.5*h; U[8]=0.25*h2;
        }
        if (t >= 1) {
            double g = (double)ST[t-1], g2 = g*g;
            D0 += 2.0;      D1 -= g;               D2 += 0.5*g2;
            D3 += g2+3.0;   D4 -= g*(0.5*g2+1.5);  D5 += g2*(0.25*g2+1.25);
            L[0]=-2.0;    L[1]=g;      L[2]=-0.5*g2;   // = U_{t-1}
            L[3]=-g;      L[4]=-3.0;   L[5]=1.5*g;
            L[6]=-0.5*g2; L[7]=-1.5*g; L[8]=0.25*g2;
        }
        fD[t][0]=(float)D0; fD[t][1]=(float)D1; fD[t][2]=(float)D2;
        fD[t][3]=(float)D3; fD[t][4]=(float)D4; fD[t][5]=(float)D5;
        #pragma unroll
        for (int k = 0; k < 9; ++k) fU[t][k] = (float)U[k];
        fb[t][0]=(float)b0; fb[t][1]=(float)b1; fb[t][2]=(float)b2;
    }
    __syncthreads();

    // -------- fp32 CR factorization: ONE barrier per level --------
    #pragma unroll
    for (int s = 1; s <= 64; s <<= 1) {
        const int m = 2*s - 1;
        if (t < NT && (t & m) == s) {
            // eliminated: publish own inverse (read own raw D only)
            float Mloc[6] = {fD[t][0],fD[t][1],fD[t][2],fD[t][3],fD[t][4],fD[t][5]};
            float I[6]; inv3_sym(Mloc, I);
            #pragma unroll
            for (int k = 0; k < 6; ++k) fDi[t][k] = I[k];
        } else if (t < NT && (t & m) == 0) {
            // survivor: recompute neighbor inverses locally from raw D
            float E[6] = {fD[t][0],fD[t][1],fD[t][2],fD[t][3],fD[t][4],fD[t][5]};
            float g0=fb[t][0], g1=fb[t][1], g2=fb[t][2];

            if (t >= s) {                       // left eliminated j = t-s
                int j = t - s;
                float Mj[6] = {fD[j][0],fD[j][1],fD[j][2],fD[j][3],fD[j][4],fD[j][5]};
                float I[6]; inv3_sym(Mj, I);
                float W0=fU[j][0],W1=fU[j][1],W2=fU[j][2];
                float W3=fU[j][3],W4=fU[j][4],W5=fU[j][5];
                float W6=fU[j][6],W7=fU[j][7],W8=fU[j][8];
                float T00=I[0]*W0+I[1]*W3+I[2]*W6, T01=I[0]*W1+I[1]*W4+I[2]*W7, T02=I[0]*W2+I[1]*W5+I[2]*W8;
                float T10=I[1]*W0+I[3]*W3+I[4]*W6, T11=I[1]*W1+I[3]*W4+I[4]*W7, T12=I[1]*W2+I[3]*W5+I[4]*W8;
                float T20=I[2]*W0+I[4]*W3+I[5]*W6, T21=I[2]*W1+I[4]*W4+I[5]*W7, T22=I[2]*W2+I[4]*W5+I[5]*W8;
                E[0] -= W0*T00 + W3*T10 + W6*T20;
                E[1] -= W0*T01 + W3*T11 + W6*T21;
                E[2] -= W0*T02 + W3*T12 + W6*T22;
                E[3] -= W1*T01 + W4*T11 + W7*T21;
                E[4] -= W1*T02 + W4*T12 + W7*T22;
                E[5] -= W2*T02 + W5*T12 + W8*T22;
                float bj0=fb[j][0], bj1=fb[j][1], bj2=fb[j][2];
                float v0=I[0]*bj0+I[1]*bj1+I[2]*bj2;
                float v1=I[1]*bj0+I[3]*bj1+I[4]*bj2;
                float v2=I[2]*bj0+I[4]*bj1+I[5]*bj2;
                g0 -= W0*v0 + W3*v1 + W6*v2;
                g1 -= W1*v0 + W4*v1 + W7*v2;
                g2 -= W2*v0 + W5*v1 + W8*v2;
            }
            if (t + s <= 99) {                  // right eliminated j = t+s
                int j = t + s;
                float Mj[6] = {fD[j][0],fD[j][1],fD[j][2],fD[j][3],fD[j][4],fD[j][5]};
                float I[6]; inv3_sym(Mj, I);
                float W0=fU[t][0],W1=fU[t][1],W2=fU[t][2];
                float W3=fU[t][3],W4=fU[t][4],W5=fU[t][5];
                float W6=fU[t][6],W7=fU[t][7],W8=fU[t][8];
                // snapshot the coupling t -> j for j's back-substitution
                fL[j][0]=W0; fL[j][1]=W1; fL[j][2]=W2;
                fL[j][3]=W3; fL[j][4]=W4; fL[j][5]=W5;
                fL[j][6]=W6; fL[j][7]=W7; fL[j][8]=W8;
                float P00=W0*I[0]+W1*I[1]+W2*I[2], P01=W0*I[1]+W1*I[3]+W2*I[4], P02=W0*I[2]+W1*I[4]+W2*I[5];
                float P10=W3*I[0]+W4*I[1]+W5*I[2], P11=W3*I[1]+W4*I[3]+W5*I[4], P12=W3*I[2]+W4*I[4]+W5*I[5];
                float P20=W6*I[0]+W7*I[1]+W8*I[2], P21=W6*I[1]+W7*I[3]+W8*I[4], P22=W6*I[2]+W7*I[4]+W8*I[5];
                E[0] -= P00*W0 + P01*W1 + P02*W2;
                E[1] -= P00*W3 + P01*W4 + P02*W5;
                E[2] -= P00*W6 + P01*W7 + P02*W8;
                E[3] -= P10*W3 + P11*W4 + P12*W5;
                E[4] -= P10*W6 + P11*W7 + P12*W8;
                E[5] -= P20*W6 + P21*W7 + P22*W8;
                float bj0=fb[j][0], bj1=fb[j][1], bj2=fb[j][2];
                g0 -= P00*bj0 + P01*bj1 + P02*bj2;
                g1 -= P10*bj0 + P11*bj1 + P12*bj2;
                g2 -= P20*bj0 + P21*bj1 + P22*bj2;
                if (t + 2*s <= 99) {            // new coupling t -> t+2s = -P * U_j
                    float V0=fU[j][0],V1=fU[j][1],V2=fU[j][2];
                    float V3=fU[j][3],V4=fU[j][4],V5=fU[j][5];
                    float V6=fU[j][6],V7=fU[j][7],V8=fU[j][8];
                    fU[t][0] = -(P00*V0 + P01*V3 + P02*V6);
                    fU[t][1] = -(P00*V1 + P01*V4 + P02*V7);
                    fU[t][2] = -(P00*V2 + P01*V5 + P02*V8);
                    fU[t][3] = -(P10*V0 + P11*V3 + P12*V6);
                    fU[t][4] = -(P10*V1 + P11*V4 + P12*V7);
                    fU[t][5] = -(P10*V2 + P11*V5 + P12*V8);
                    fU[t][6] = -(P20*V0 + P21*V3 + P22*V6);
                    fU[t][7] = -(P20*V1 + P21*V4 + P22*V7);
                    fU[t][8] = -(P20*V2 + P21*V5 + P22*V8);
                }
            }
            fD[t][0]=E[0]; fD[t][1]=E[1]; fD[t][2]=E[2];
            fD[t][3]=E[3]; fD[t][4]=E[4]; fD[t][5]=E[5];
            fb[t][0]=g0;  fb[t][1]=g1;  fb[t][2]=g2;
        }
        __syncthreads();
    }

    // -------- root: invert D0 (stored for refinement), first solve x0 --------
    if (t == 0) {
        float Mloc[6] = {fD[0][0],fD[0][1],fD[0][2],fD[0][3],fD[0][4],fD[0][5]};
        float I[6]; inv3_sym(Mloc, I);
        #pragma unroll
        for (int k = 0; k < 6; ++k) fDi[0][k] = I[k];
        float g0=fb[0][0], g1=fb[0][1], g2=fb[0][2];
        fx[0][0] = I[0]*g0 + I[1]*g1 + I[2]*g2;
        fx[0][1] = I[1]*g0 + I[3]*g1 + I[4]*g2;
        fx[0][2] = I[2]*g0 + I[4]*g1 + I[5]*g2;
    }
    __syncthreads();

    // -------- back substitution (first solve) --------
    #pragma unroll
    for (int s = 64; s >= 1; s >>= 1) {
        if (t < NT && (t & (2*s-1)) == s) {
            float r0=fb[t][0], r1=fb[t][1], r2=fb[t][2];
            float xl0=fx[t-s][0], xl1=fx[t-s][1], xl2=fx[t-s][2];
            r0 -= fL[t][0]*xl0 + fL[t][3]*xl1 + fL[t][6]*xl2;
            r1 -= fL[t][1]*xl0 + fL[t][4]*xl1 + fL[t][7]*xl2;
            r2 -= fL[t][2]*xl0 + fL[t][5]*xl1 + fL[t][8]*xl2;
            if (t + s <= 99) {
                float xr0=fx[t+s][0], xr1=fx[t+s][1], xr2=fx[t+s][2];
                r0 -= fU[t][0]*xr0 + fU[t][1]*xr1 + fU[t][2]*xr2;
                r1 -= fU[t][3]*xr0 + fU[t][4]*xr1 + fU[t][5]*xr2;
                r2 -= fU[t][6]*xr0 + fU[t][7]*xr1 + fU[t][8]*xr2;
            }
            fx[t][0] = fDi[t][0]*r0 + fDi[t][1]*r1 + fDi[t][2]*r2;
            fx[t][1] = fDi[t][1]*r0 + fDi[t][3]*r1 + fDi[t][4]*r2;
            fx[t][2] = fDi[t][2]*r0 + fDi[t][4]*r1 + fDi[t][5]*r2;
        }
        __syncthreads();
    }

    // -------- one fp64 refinement: residual against exact matrix --------
    double x0=0, x1=0, x2=0;
    if (t < NT) {
        x0=fx[t][0]; x1=fx[t][1]; x2=fx[t][2];
        double r0 = b0 - (D0*x0 + D1*x1 + D2*x2);
        double r1 = b1 - (D1*x0 + D3*x1 + D4*x2);
        double r2 = b2 - (D2*x0 + D4*x1 + D5*x2);
        if (t < 99) {
            double y0=fx[t+1][0], y1=fx[t+1][1], y2=fx[t+1][2];
            r0 -= U[0]*y0 + U[1]*y1 + U[2]*y2;
            r1 -= U[3]*y0 + U[4]*y1 + U[5]*y2;
            r2 -= U[6]*y0 + U[7]*y1 + U[8]*y2;
        }
        if (t >= 1) {
            double y0=fx[t-1][0], y1=fx[t-1][1], y2=fx[t-1][2];
            r0 -= L[0]*y0 + L[3]*y1 + L[6]*y2;
            r1 -= L[1]*y0 + L[4]*y1 + L[7]*y2;
            r2 -= L[2]*y0 + L[5]*y1 + L[8]*y2;
        }
        fb[t][0]=(float)r0; fb[t][1]=(float)r1; fb[t][2]=(float)r2;
    }
    __syncthreads();

    // forward rhs elimination with stored factors
    #pragma unroll
    for (int s = 1; s <= 64; s <<= 1) {
        if (t < NT && (t & (2*s-1)) == 0) {
            float g0=fb[t][0], g1=fb[t][1], g2=fb[t][2];
            if (t >= s) {
                int j = t - s;
                float bj0=fb[j][0], bj1=fb[j][1], bj2=fb[j][2];
                float v0=fDi[j][0]*bj0+fDi[j][1]*bj1+fDi[j][2]*bj2;
                float v1=fDi[j][1]*bj0+fDi[j][3]*bj1+fDi[j][4]*bj2;
                float v2=fDi[j][2]*bj0+fDi[j][4]*bj1+fDi[j][5]*bj2;
                g0 -= fU[j][0]*v0 + fU[j][3]*v1 + fU[j][6]*v2;
                g1 -= fU[j][1]*v0 + fU[j][4]*v1 + fU[j][7]*v2;
                g2 -= fU[j][2]*v0 + fU[j][5]*v1 + fU[j][8]*v2;
            }
            if (t + s <= 99) {
                int j = t + s;   // coupling t->j is fL[j]
                float bj0=fb[j][0], bj1=fb[j][1], bj2=fb[j][2];
                float v0=fDi[j][0]*bj0+fDi[j][1]*bj1+fDi[j][2]*bj2;
                float v1=fDi[j][1]*bj0+fDi[j][3]*bj1+fDi[j][4]*bj2;
                float v2=fDi[j][2]*bj0+fDi[j][4]*bj1+fDi[j][5]*bj2;
                g0 -= fL[j][0]*v0 + fL[j][1]*v1 + fL[j][2]*v2;
                g1 -= fL[j][3]*v0 + fL[j][4]*v1 + fL[j][5]*v2;
                g2 -= fL[j][6]*v0 + fL[j][7]*v1 + fL[j][8]*v2;
            }
            fb[t][0]=g0; fb[t][1]=g1; fb[t][2]=g2;
        }
        __syncthreads();
    }
    if (t == 0) {
        float g0=fb[0][0], g1=fb[0][1], g2=fb[0][2];
        fx[0][0] = fDi[0][0]*g0 + fDi[0][1]*g1 + fDi[0][2]*g2;
        fx[0][1] = fDi[0][1]*g0 + fDi[0][3]*g1 + fDi[0][4]*g2;
        fx[0][2] = fDi[0][2]*g0 + fDi[0][4]*g1 + fDi[0][5]*g2;
    }
    __syncthreads();
    #pragma unroll
    for (int s = 64; s >= 1; s >>= 1) {
        if (t < NT && (t & (2*s-1)) == s) {
            float r0=fb[t][0], r1=fb[t][1], r2=fb[t][2];
            float xl0=fx[t-s][0], xl1=fx[t-s][1], xl2=fx[t-s][2];
            r0 -= fL[t][0]*xl0 + fL[t][3]*xl1 + fL[t][6]*xl2;
            r1 -= fL[t][1]*xl0 + fL[t][4]*xl1 + fL[t][7]*xl2;
            r2 -= fL[t][2]*xl0 + fL[t][5]*xl1 + fL[t][8]*xl2;
            if (t + s <= 99) {
                float xr0=fx[t+s][0], xr1=fx[t+s][1], xr2=fx[t+s][2];
                r0 -= fU[t][0]*xr0 + fU[t][1]*xr1 + fU[t][2]*xr2;
                r1 -= fU[t][3]*xr0 + fU[t][4]*xr1 + fU[t][5]*xr2;
                r2 -= fU[t][6]*xr0 + fU[t][7]*xr1 + fU[t][8]*xr2;
            }
            fx[t][0] = fDi[t][0]*r0 + fDi[t][1]*r1 + fDi[t][2]*r2;
            fx[t][1] = fDi[t][1]*r0 + fDi[t][3]*r1 + fDi[t][4]*r2;
            fx[t][2] = fDi[t][2]*r0 + fDi[t][4]*r1 + fDi[t][5]*r2;
        }
        __syncthreads();
    }

    // -------- outputs: first solution + correction --------
    if (t < NT) {
        out[        sys*100 + t] = (float)(x0 + (double)fx[t][0]);
        out[25600 + sys*100 + t] = (float)(x1 + (double)fx[t][1]);
        out[51200 + sys*100 + t] = (float)(x2 + (double)fx[t][2]);
    }
    if (t == 0) out[76800 + sys] = 0.0f;
    if (t < 99) out[77056 + sys*99 + t] = st_local;
}

extern "C" void kernel_launch(void* const* d_in, const int* in_sizes, int n_in,
                              void* d_out, int out_size)
{
    (void)out_size;
    const float* coeffs = nullptr;
    const float* rhs    = nullptr;
    const float* iv_rhs = nullptr;
    const float* steps  = nullptr;
    for (int i = 0; i < n_in; ++i) {
        switch (in_sizes[i]) {
            case 76800: coeffs = (const float*)d_in[i]; break;
            case 25600: rhs    = (const float*)d_in[i]; break;
            case 512:   iv_rhs = (const float*)d_in[i]; break;
            case 25344: steps  = (const float*)d_in[i]; break;
            default: break;
        }
    }
    if (!coeffs && n_in > 0) coeffs = (const float*)d_in[0];
    if (!rhs    && n_in > 1) rhs    = (const float*)d_in[1];
    if (!iv_rhs && n_in > 2) iv_rhs = (const float*)d_in[2];
    if (!steps  && n_in > 3) steps  = (const float*)d_in[3];

    ode_cr_fused_kernel<<<NSYS, 128>>>(coeffs, rhs, iv_rhs, steps, (float*)d_out);
}

// round 7
// speedup vs baseline: 51.8776x; 2.1195x over previous
#include <cuda_runtime.h>

// ODEINDLayer: 256 independent SPD block-tridiagonal systems (100 blocks of
// 3x3). Pure-fp32 block cyclic reduction, fused phases (one barrier per
// level), no refinement (measured fp32-solve rel_err ~4e-5 << 1e-3).
// One CTA per system, one thread per time-node.
//
// Blocks (ORDER=2), from the reference's Dt/Dt1:
//   D_t = c_t c_t^T + [t<99] G(h_t) + [t>=1] H(h_{t-1}) + [t==0] diag(1,1,0)
//   U_t = C(h_t) = [[-2,h,-h^2/2],[-h,-3,1.5h],[-h^2/2,-1.5h,h^2/4]]
//   L_{t+1} = U_t^T ; rhs_t = c_t*r_t + [t==0](iv0,iv1,0)

#define NSYS 256
#define NT   100

// Invert symmetric 3x3 (packed 00,01,02,11,12,22) via adjugate, exact division.
__device__ __forceinline__ void inv3_sym(const float M[6], float I[6]) {
    float A00 = M[3]*M[5] - M[4]*M[4];
    float A01 = M[2]*M[4] - M[1]*M[5];
    float A02 = M[1]*M[4] - M[2]*M[3];
    float A11 = M[0]*M[5] - M[2]*M[2];
    float A12 = M[1]*M[2] - M[0]*M[4];
    float A22 = M[0]*M[3] - M[1]*M[1];
    float id  = 1.0f / (M[0]*A00 + M[1]*A01 + M[2]*A02);
    I[0]=A00*id; I[1]=A01*id; I[2]=A02*id; I[3]=A11*id; I[4]=A12*id; I[5]=A22*id;
}

__global__ __launch_bounds__(128)
void ode_cr32_kernel(const float* __restrict__ coeffs,
                     const float* __restrict__ rhs,
                     const float* __restrict__ iv_rhs,
                     const float* __restrict__ steps,
                     float* __restrict__ out)
{
    __shared__ float fD[NT][6];   // raw diag; frozen for eliminated nodes at their level
    __shared__ float fU[NT][9];   // coupling t -> t+stride (frozen at elimination)
    __shared__ float fL[NT][9];   // snapshot: coupling (t-s) -> t at elimination level
    __shared__ float fb[NT][3];   // rhs (frozen for eliminated nodes)
    __shared__ float fx[NT][3];   // solution

    const int sys = blockIdx.x;
    const int t   = threadIdx.x;

    const float* C  = coeffs + sys * 300;
    const float* R  = rhs    + sys * 100;
    const float* IV = iv_rhs + sys * 2;
    const float* ST = steps  + sys * 99;

    float st_local = 0.0f;

    // ---------------- fp32 build ----------------
    if (t < NT) {
        float c0 = C[3*t], c1 = C[3*t+1], c2 = C[3*t+2];
        float rt = R[t];
        float D0=c0*c0, D1=c0*c1, D2=c0*c2, D3=c1*c1, D4=c1*c2, D5=c2*c2;
        float b0=c0*rt, b1=c1*rt, b2=c2*rt;
        if (t == 0) { D0 += 1.0f; D3 += 1.0f; b0 += IV[0]; b1 += IV[1]; }
        if (t < 99) {
            st_local = ST[t];
            float h = st_local, h2 = h*h;
            D0 += 2.0f;       D1 += h;                 D2 += 0.5f*h2;
            D3 += h2+3.0f;    D4 += h*(0.5f*h2+1.5f);  D5 += h2*(0.25f*h2+1.25f);
            fU[t][0]=-2.0f;    fU[t][1]=h;       fU[t][2]=-0.5f*h2;
            fU[t][3]=-h;       fU[t][4]=-3.0f;   fU[t][5]=1.5f*h;
            fU[t][6]=-0.5f*h2; fU[t][7]=-1.5f*h; fU[t][8]=0.25f*h2;
        }
        if (t >= 1) {
            float g = ST[t-1], g2 = g*g;
            D0 += 2.0f;       D1 -= g;                 D2 += 0.5f*g2;
            D3 += g2+3.0f;    D4 -= g*(0.5f*g2+1.5f);  D5 += g2*(0.25f*g2+1.25f);
        }
        fD[t][0]=D0; fD[t][1]=D1; fD[t][2]=D2; fD[t][3]=D3; fD[t][4]=D4; fD[t][5]=D5;
        fb[t][0]=b0; fb[t][1]=b1; fb[t][2]=b2;
    }
    __syncthreads();

    // ---------------- CR factorization: one barrier per level ----------------
    // Only survivors are active; they recompute neighbor inverses locally from
    // the (frozen) raw fD of eliminated neighbors.
    #pragma unroll
    for (int s = 1; s <= 64; s <<= 1) {
        const int m = 2*s - 1;
        if (t < NT && (t & m) == 0) {
            float E[6] = {fD[t][0],fD[t][1],fD[t][2],fD[t][3],fD[t][4],fD[t][5]};
            float g0=fb[t][0], g1=fb[t][1], g2=fb[t][2];

            if (t >= s) {                       // left eliminated j = t-s
                int j = t - s;
                float Mj[6] = {fD[j][0],fD[j][1],fD[j][2],fD[j][3],fD[j][4],fD[j][5]};
                float I[6]; inv3_sym(Mj, I);
                float W0=fU[j][0],W1=fU[j][1],W2=fU[j][2];
                float W3=fU[j][3],W4=fU[j][4],W5=fU[j][5];
                float W6=fU[j][6],W7=fU[j][7],W8=fU[j][8];
                float T00=I[0]*W0+I[1]*W3+I[2]*W6, T01=I[0]*W1+I[1]*W4+I[2]*W7, T02=I[0]*W2+I[1]*W5+I[2]*W8;
                float T10=I[1]*W0+I[3]*W3+I[4]*W6, T11=I[1]*W1+I[3]*W4+I[4]*W7, T12=I[1]*W2+I[3]*W5+I[4]*W8;
                float T20=I[2]*W0+I[4]*W3+I[5]*W6, T21=I[2]*W1+I[4]*W4+I[5]*W7, T22=I[2]*W2+I[4]*W5+I[5]*W8;
                E[0] -= W0*T00 + W3*T10 + W6*T20;
                E[1] -= W0*T01 + W3*T11 + W6*T21;
                E[2] -= W0*T02 + W3*T12 + W6*T22;
                E[3] -= W1*T01 + W4*T11 + W7*T21;
                E[4] -= W1*T02 + W4*T12 + W7*T22;
                E[5] -= W2*T02 + W5*T12 + W8*T22;
                float bj0=fb[j][0], bj1=fb[j][1], bj2=fb[j][2];
                float v0=I[0]*bj0+I[1]*bj1+I[2]*bj2;
                float v1=I[1]*bj0+I[3]*bj1+I[4]*bj2;
                float v2=I[2]*bj0+I[4]*bj1+I[5]*bj2;
                g0 -= W0*v0 + W3*v1 + W6*v2;
                g1 -= W1*v0 + W4*v1 + W7*v2;
                g2 -= W2*v0 + W5*v1 + W8*v2;
            }
            if (t + s <= 99) {                  // right eliminated j = t+s
                int j = t + s;
                float Mj[6] = {fD[j][0],fD[j][1],fD[j][2],fD[j][3],fD[j][4],fD[j][5]};
                float I[6]; inv3_sym(Mj, I);
                float W0=fU[t][0],W1=fU[t][1],W2=fU[t][2];
                float W3=fU[t][3],W4=fU[t][4],W5=fU[t][5];
                float W6=fU[t][6],W7=fU[t][7],W8=fU[t][8];
                // snapshot coupling t -> j for j's back-substitution
                fL[j][0]=W0; fL[j][1]=W1; fL[j][2]=W2;
                fL[j][3]=W3; fL[j][4]=W4; fL[j][5]=W5;
                fL[j][6]=W6; fL[j][7]=W7; fL[j][8]=W8;
                float P00=W0*I[0]+W1*I[1]+W2*I[2], P01=W0*I[1]+W1*I[3]+W2*I[4], P02=W0*I[2]+W1*I[4]+W2*I[5];
                float P10=W3*I[0]+W4*I[1]+W5*I[2], P11=W3*I[1]+W4*I[3]+W5*I[4], P12=W3*I[2]+W4*I[4]+W5*I[5];
                float P20=W6*I[0]+W7*I[1]+W8*I[2], P21=W6*I[1]+W7*I[3]+W8*I[4], P22=W6*I[2]+W7*I[4]+W8*I[5];
                E[0] -= P00*W0 + P01*W1 + P02*W2;
                E[1] -= P00*W3 + P01*W4 + P02*W5;
                E[2] -= P00*W6 + P01*W7 + P02*W8;
                E[3] -= P10*W3 + P11*W4 + P12*W5;
                E[4] -= P10*W6 + P11*W7 + P12*W8;
                E[5] -= P20*W6 + P21*W7 + P22*W8;
                float bj0=fb[j][0], bj1=fb[j][1], bj2=fb[j][2];
                g0 -= P00*bj0 + P01*bj1 + P02*bj2;
                g1 -= P10*bj0 + P11*bj1 + P12*bj2;
                g2 -= P20*bj0 + P21*bj1 + P22*bj2;
                if (t + 2*s <= 99) {            // new coupling t -> t+2s = -P * U_j
                    float V0=fU[j][0],V1=fU[j][1],V2=fU[j][2];
                    float V3=fU[j][3],V4=fU[j][4],V5=fU[j][5];
                    float V6=fU[j][6],V7=fU[j][7],V8=fU[j][8];
                    fU[t][0] = -(P00*V0 + P01*V3 + P02*V6);
                    fU[t][1] = -(P00*V1 + P01*V4 + P02*V7);
                    fU[t][2] = -(P00*V2 + P01*V5 + P02*V8);
                    fU[t][3] = -(P10*V0 + P11*V3 + P12*V6);
                    fU[t][4] = -(P10*V1 + P11*V4 + P12*V7);
                    fU[t][5] = -(P10*V2 + P11*V5 + P12*V8);
                    fU[t][6] = -(P20*V0 + P21*V3 + P22*V6);
                    fU[t][7] = -(P20*V1 + P21*V4 + P22*V7);
                    fU[t][8] = -(P20*V2 + P21*V5 + P22*V8);
                }
            }
            fD[t][0]=E[0]; fD[t][1]=E[1]; fD[t][2]=E[2];
            fD[t][3]=E[3]; fD[t][4]=E[4]; fD[t][5]=E[5];
            fb[t][0]=g0;  fb[t][1]=g1;  fb[t][2]=g2;
        }
        __syncthreads();
    }

    // ---------------- back substitution (root folded into s=64 phase) ----------------
    #pragma unroll
    for (int s = 64; s >= 1; s >>= 1) {
        if (s == 64 && t == 0) {
            // root solve: x0 = inv(fD[0]) * fb[0]
            float M0[6] = {fD[0][0],fD[0][1],fD[0][2],fD[0][3],fD[0][4],fD[0][5]};
            float I[6]; inv3_sym(M0, I);
            float g0=fb[0][0], g1=fb[0][1], g2=fb[0][2];
            fx[0][0] = I[0]*g0 + I[1]*g1 + I[2]*g2;
            fx[0][1] = I[1]*g0 + I[3]*g1 + I[4]*g2;
            fx[0][2] = I[2]*g0 + I[4]*g1 + I[5]*g2;
        }
        if (t < NT && (t & (2*s-1)) == s) {
            float r0=fb[t][0], r1=fb[t][1], r2=fb[t][2];
            float xl0, xl1, xl2;
            if (s == 64) {
                // t==64 needs x0, computed in this same phase by t==0; recompute
                // it locally instead of waiting for a barrier.
                float M0[6] = {fD[0][0],fD[0][1],fD[0][2],fD[0][3],fD[0][4],fD[0][5]};
                float I[6]; inv3_sym(M0, I);
                float g0=fb[0][0], g1=fb[0][1], g2=fb[0][2];
                xl0 = I[0]*g0 + I[1]*g1 + I[2]*g2;
                xl1 = I[1]*g0 + I[3]*g1 + I[4]*g2;
                xl2 = I[2]*g0 + I[4]*g1 + I[5]*g2;
            } else {
                xl0=fx[t-s][0]; xl1=fx[t-s][1]; xl2=fx[t-s][2];
            }
            r0 -= fL[t][0]*xl0 + fL[t][3]*xl1 + fL[t][6]*xl2;
            r1 -= fL[t][1]*xl0 + fL[t][4]*xl1 + fL[t][7]*xl2;
            r2 -= fL[t][2]*xl0 + fL[t][5]*xl1 + fL[t][8]*xl2;
            if (t + s <= 99) {
                float xr0=fx[t+s][0], xr1=fx[t+s][1], xr2=fx[t+s][2];
                r0 -= fU[t][0]*xr0 + fU[t][1]*xr1 + fU[t][2]*xr2;
                r1 -= fU[t][3]*xr0 + fU[t][4]*xr1 + fU[t][5]*xr2;
                r2 -= fU[t][6]*xr0 + fU[t][7]*xr1 + fU[t][8]*xr2;
            }
            // invert own frozen raw diag
            float Mt[6] = {fD[t][0],fD[t][1],fD[t][2],fD[t][3],fD[t][4],fD[t][5]};
            float I[6]; inv3_sym(Mt, I);
            fx[t][0] = I[0]*r0 + I[1]*r1 + I[2]*r2;
            fx[t][1] = I[1]*r0 + I[3]*r1 + I[4]*r2;
            fx[t][2] = I[2]*r0 + I[4]*r1 + I[5]*r2;
        }
        __syncthreads();
    }

    // ---------------- outputs ----------------
    if (t < NT) {
        out[        sys*100 + t] = fx[t][0];
        out[25600 + sys*100 + t] = fx[t][1];
        out[51200 + sys*100 + t] = fx[t][2];
    }
    if (t == 0) out[76800 + sys] = 0.0f;
    if (t < 99) out[77056 + sys*99 + t] = st_local;
}

extern "C" void kernel_launch(void* const* d_in, const int* in_sizes, int n_in,
                              void* d_out, int out_size)
{
    (void)out_size;
    const float* coeffs = nullptr;
    const float* rhs    = nullptr;
    const float* iv_rhs = nullptr;
    const float* steps  = nullptr;
    for (int i = 0; i < n_in; ++i) {
        switch (in_sizes[i]) {
            case 76800: coeffs = (const float*)d_in[i]; break;
            case 25600: rhs    = (const float*)d_in[i]; break;
            case 512:   iv_rhs = (const float*)d_in[i]; break;
            case 25344: steps  = (const float*)d_in[i]; break;
            default: break;
        }
    }
    if (!coeffs && n_in > 0) coeffs = (const float*)d_in[0];
    if (!rhs    && n_in > 1) rhs    = (const float*)d_in[1];
    if (!iv_rhs && n_in > 2) iv_rhs = (const float*)d_in[2];
    if (!steps  && n_in > 3) steps  = (const float*)d_in[3];

    ode_cr32_kernel<<<NSYS, 128>>>(coeffs, rhs, iv_rhs, steps, (float*)d_out);
}

// round 8
// speedup vs baseline: 60.9384x; 1.1747x over previous
#include <cuda_runtime.h>

// ODEINDLayer: 256 independent SPD block-tridiagonal systems (100 blocks of
// 3x3). PARALLEL cyclic reduction (PCR), pure fp32: 7 levels, all nodes
// active each level, no back-substitution. One CTA per system, one thread
// per time-node. Double-buffered shared state, one barrier per level.
//
// Node equation at stride s:  L_i x_{i-s} + D_i x_i + U_i x_{i+s} = b_i,
// with L_i = U_{i-s}^T (preserved across levels). Level update:
//   left  j=i-s: Ij=inv(D_j); T=Ij*U_j;  D_i -= U_j^T T;  b_i -= U_j^T (Ij b_j)
//   right j=i+s: Ij=inv(D_j); P=U_i*Ij;  D_i -= P U_i^T;  b_i -= P b_j;
//                U_i' = -P U_j (iff i+2s <= 99)
// After stride >= 100: x_i = inv(D_i) b_i.

#define NSYS 256
#define NT   100

__device__ __forceinline__ void inv3_sym(const float M[6], float I[6]) {
    float A00 = M[3]*M[5] - M[4]*M[4];
    float A01 = M[2]*M[4] - M[1]*M[5];
    float A02 = M[1]*M[4] - M[2]*M[3];
    float A11 = M[0]*M[5] - M[2]*M[2];
    float A12 = M[1]*M[2] - M[0]*M[4];
    float A22 = M[0]*M[3] - M[1]*M[1];
    float id  = 1.0f / (M[0]*A00 + M[1]*A01 + M[2]*A02);
    I[0]=A00*id; I[1]=A01*id; I[2]=A02*id; I[3]=A11*id; I[4]=A12*id; I[5]=A22*id;
}

__global__ __launch_bounds__(128)
void ode_pcr32_kernel(const float* __restrict__ coeffs,
                      const float* __restrict__ rhs,
                      const float* __restrict__ iv_rhs,
                      const float* __restrict__ steps,
                      float* __restrict__ out)
{
    // Double-buffered node state; odd row strides -> conflict-free LDS.
    __shared__ float sD[2][NT][7];   // sym diag: 00,01,02,11,12,22 (+pad)
    __shared__ float sU[2][NT][9];   // coupling i -> i+stride
    __shared__ float sb[2][NT][3];   // rhs

    const int sys = blockIdx.x;
    const int t   = threadIdx.x;

    const float* C  = coeffs + sys * 300;
    const float* R  = rhs    + sys * 100;
    const float* IV = iv_rhs + sys * 2;
    const float* ST = steps  + sys * 99;

    float st_local = 0.0f;

    // Register copy of own state (always current).
    float D[6] = {0,0,0,0,0,0};
    float U[9] = {0,0,0,0,0,0,0,0,0};
    float B[3] = {0,0,0};

    // ---------------- build (buffer 0) ----------------
    if (t < NT) {
        float c0 = C[3*t], c1 = C[3*t+1], c2 = C[3*t+2];
        float rt = R[t];
        D[0]=c0*c0; D[1]=c0*c1; D[2]=c0*c2; D[3]=c1*c1; D[4]=c1*c2; D[5]=c2*c2;
        B[0]=c0*rt; B[1]=c1*rt; B[2]=c2*rt;
        if (t == 0) { D[0] += 1.0f; D[3] += 1.0f; B[0] += IV[0]; B[1] += IV[1]; }
        if (t < 99) {
            st_local = ST[t];
            float h = st_local, h2 = h*h;
            D[0] += 2.0f;      D[1] += h;                D[2] += 0.5f*h2;
            D[3] += h2+3.0f;   D[4] += h*(0.5f*h2+1.5f); D[5] += h2*(0.25f*h2+1.25f);
            U[0]=-2.0f;    U[1]=h;       U[2]=-0.5f*h2;
            U[3]=-h;       U[4]=-3.0f;   U[5]=1.5f*h;
            U[6]=-0.5f*h2; U[7]=-1.5f*h; U[8]=0.25f*h2;
        }
        if (t >= 1) {
            float g = ST[t-1], g2 = g*g;
            D[0] += 2.0f;      D[1] -= g;                D[2] += 0.5f*g2;
            D[3] += g2+3.0f;   D[4] -= g*(0.5f*g2+1.5f); D[5] += g2*(0.25f*g2+1.25f);
        }
        #pragma unroll
        for (int k = 0; k < 6; ++k) sD[0][t][k] = D[k];
        #pragma unroll
        for (int k = 0; k < 9; ++k) sU[0][t][k] = U[k];
        #pragma unroll
        for (int k = 0; k < 3; ++k) sb[0][t][k] = B[k];
    }
    __syncthreads();

    // ---------------- 7 PCR levels ----------------
    #pragma unroll
    for (int lvl = 0; lvl < 7; ++lvl) {
        const int s   = 1 << lvl;
        const int cur = lvl & 1;
        const int nxt = cur ^ 1;

        if (t < NT) {
            if (t >= s) {                        // left neighbor j = t-s
                const int j = t - s;
                float Mj[6] = {sD[cur][j][0],sD[cur][j][1],sD[cur][j][2],
                               sD[cur][j][3],sD[cur][j][4],sD[cur][j][5]};
                float I[6]; inv3_sym(Mj, I);
                float W0=sU[cur][j][0],W1=sU[cur][j][1],W2=sU[cur][j][2];
                float W3=sU[cur][j][3],W4=sU[cur][j][4],W5=sU[cur][j][5];
                float W6=sU[cur][j][6],W7=sU[cur][j][7],W8=sU[cur][j][8];
                // T = I * W
                float T00=I[0]*W0+I[1]*W3+I[2]*W6, T01=I[0]*W1+I[1]*W4+I[2]*W7, T02=I[0]*W2+I[1]*W5+I[2]*W8;
                float T10=I[1]*W0+I[3]*W3+I[4]*W6, T11=I[1]*W1+I[3]*W4+I[4]*W7, T12=I[1]*W2+I[3]*W5+I[4]*W8;
                float T20=I[2]*W0+I[4]*W3+I[5]*W6, T21=I[2]*W1+I[4]*W4+I[5]*W7, T22=I[2]*W2+I[4]*W5+I[5]*W8;
                // D -= W^T T  (symmetric)
                D[0] -= W0*T00 + W3*T10 + W6*T20;
                D[1] -= W0*T01 + W3*T11 + W6*T21;
                D[2] -= W0*T02 + W3*T12 + W6*T22;
                D[3] -= W1*T01 + W4*T11 + W7*T21;
                D[4] -= W1*T02 + W4*T12 + W7*T22;
                D[5] -= W2*T02 + W5*T12 + W8*T22;
                // b -= W^T (I * b_j)
                float bj0=sb[cur][j][0], bj1=sb[cur][j][1], bj2=sb[cur][j][2];
                float v0=I[0]*bj0+I[1]*bj1+I[2]*bj2;
                float v1=I[1]*bj0+I[3]*bj1+I[4]*bj2;
                float v2=I[2]*bj0+I[4]*bj1+I[5]*bj2;
                B[0] -= W0*v0 + W3*v1 + W6*v2;
                B[1] -= W1*v0 + W4*v1 + W7*v2;
                B[2] -= W2*v0 + W5*v1 + W8*v2;
            }
            if (t + s <= 99) {                   // right neighbor j = t+s
                const int j = t + s;
                float Mj[6] = {sD[cur][j][0],sD[cur][j][1],sD[cur][j][2],
                               sD[cur][j][3],sD[cur][j][4],sD[cur][j][5]};
                float I[6]; inv3_sym(Mj, I);
                // P = U * I   (U = own coupling, registers)
                float P00=U[0]*I[0]+U[1]*I[1]+U[2]*I[2], P01=U[0]*I[1]+U[1]*I[3]+U[2]*I[4], P02=U[0]*I[2]+U[1]*I[4]+U[2]*I[5];
                float P10=U[3]*I[0]+U[4]*I[1]+U[5]*I[2], P11=U[3]*I[1]+U[4]*I[3]+U[5]*I[4], P12=U[3]*I[2]+U[4]*I[4]+U[5]*I[5];
                float P20=U[6]*I[0]+U[7]*I[1]+U[8]*I[2], P21=U[6]*I[1]+U[7]*I[3]+U[8]*I[4], P22=U[6]*I[2]+U[7]*I[4]+U[8]*I[5];
                // D -= P U^T  (symmetric)
                D[0] -= P00*U[0] + P01*U[1] + P02*U[2];
                D[1] -= P00*U[3] + P01*U[4] + P02*U[5];
                D[2] -= P00*U[6] + P01*U[7] + P02*U[8];
                D[3] -= P10*U[3] + P11*U[4] + P12*U[5];
                D[4] -= P10*U[6] + P11*U[7] + P12*U[8];
                D[5] -= P20*U[6] + P21*U[7] + P22*U[8];
                // b -= P b_j
                float bj0=sb[cur][j][0], bj1=sb[cur][j][1], bj2=sb[cur][j][2];
                B[0] -= P00*bj0 + P01*bj1 + P02*bj2;
                B[1] -= P10*bj0 + P11*bj1 + P12*bj2;
                B[2] -= P20*bj0 + P21*bj1 + P22*bj2;
                // U' = -P U_j  (coupling t -> t+2s), else dead
                if (t + 2*s <= 99) {
                    float V0=sU[cur][j][0],V1=sU[cur][j][1],V2=sU[cur][j][2];
                    float V3=sU[cur][j][3],V4=sU[cur][j][4],V5=sU[cur][j][5];
                    float V6=sU[cur][j][6],V7=sU[cur][j][7],V8=sU[cur][j][8];
                    float N0 = -(P00*V0 + P01*V3 + P02*V6);
                    float N1 = -(P00*V1 + P01*V4 + P02*V7);
                    float N2 = -(P00*V2 + P01*V5 + P02*V8);
                    float N3 = -(P10*V0 + P11*V3 + P12*V6);
                    float N4 = -(P10*V1 + P11*V4 + P12*V7);
                    float N5 = -(P10*V2 + P11*V5 + P12*V8);
                    float N6 = -(P20*V0 + P21*V3 + P22*V6);
                    float N7 = -(P20*V1 + P21*V4 + P22*V7);
                    float N8 = -(P20*V2 + P21*V5 + P22*V8);
                    U[0]=N0; U[1]=N1; U[2]=N2; U[3]=N3; U[4]=N4; U[5]=N5; U[6]=N6; U[7]=N7; U[8]=N8;
                }
            }
        }

        // Publish for the next level (skip after the last level).
        if (lvl < 6) {
            if (t < NT) {
                #pragma unroll
                for (int k = 0; k < 6; ++k) sD[nxt][t][k] = D[k];
                #pragma unroll
                for (int k = 0; k < 9; ++k) sU[nxt][t][k] = U[k];
                #pragma unroll
                for (int k = 0; k < 3; ++k) sb[nxt][t][k] = B[k];
            }
            __syncthreads();
        }
    }

    // ---------------- diagonal solve + outputs ----------------
    if (t < NT) {
        float I[6]; inv3_sym(D, I);
        float x0 = I[0]*B[0] + I[1]*B[1] + I[2]*B[2];
        float x1 = I[1]*B[0] + I[3]*B[1] + I[4]*B[2];
        float x2 = I[2]*B[0] + I[4]*B[1] + I[5]*B[2];
        out[        sys*100 + t] = x0;
        out[25600 + sys*100 + t] = x1;
        out[51200 + sys*100 + t] = x2;
    }
    if (t == 0) out[76800 + sys] = 0.0f;
    if (t < 99) out[77056 + sys*99 + t] = st_local;
}

extern "C" void kernel_launch(void* const* d_in, const int* in_sizes, int n_in,
                              void* d_out, int out_size)
{
    (void)out_size;
    const float* coeffs = nullptr;
    const float* rhs    = nullptr;
    const float* iv_rhs = nullptr;
    const float* steps  = nullptr;
    for (int i = 0; i < n_in; ++i) {
        switch (in_sizes[i]) {
            case 76800: coeffs = (const float*)d_in[i]; break;
            case 25600: rhs    = (const float*)d_in[i]; break;
            case 512:   iv_rhs = (const float*)d_in[i]; break;
            case 25344: steps  = (const float*)d_in[i]; break;
            default: break;
        }
    }
    if (!coeffs && n_in > 0) coeffs = (const float*)d_in[0];
    if (!rhs    && n_in > 1) rhs    = (const float*)d_in[1];
    if (!iv_rhs && n_in > 2) iv_rhs = (const float*)d_in[2];
    if (!steps  && n_in > 3) steps  = (const float*)d_in[3];

    ode_pcr32_kernel<<<NSYS, 128>>>(coeffs, rhs, iv_rhs, steps, (float*)d_out);
}

// round 9
// speedup vs baseline: 63.7778x; 1.0466x over previous
#include <cuda_runtime.h>

// ODEINDLayer: 256 independent SPD block-tridiagonal systems (100 blocks of
// 3x3). Parallel cyclic reduction, pure fp32. Level 0 fused into registers
// (each thread rebuilds its neighbors' initial blocks from closed-form
// inputs); levels 1..6 via float4-packed double-buffered shared memory,
// one barrier per level. rcp.approx+Newton for 3x3 inverses.

#define NSYS 256
#define NT   100

__device__ __forceinline__ float frcp_nr(float x) {
    float r; asm("rcp.approx.f32 %0, %1;" : "=f"(r) : "f"(x));
    return r * (2.0f - x * r);
}

// Inverse of symmetric 3x3 (packed 00,01,02,11,12,22).
__device__ __forceinline__ void inv3_sym(const float M[6], float I[6]) {
    float A00 = M[3]*M[5] - M[4]*M[4];
    float A01 = M[2]*M[4] - M[1]*M[5];
    float A02 = M[1]*M[4] - M[2]*M[3];
    float A11 = M[0]*M[5] - M[2]*M[2];
    float A12 = M[1]*M[2] - M[0]*M[4];
    float A22 = M[0]*M[3] - M[1]*M[1];
    float id  = frcp_nr(M[0]*A00 + M[1]*A01 + M[2]*A02);
    I[0]=A00*id; I[1]=A01*id; I[2]=A02*id; I[3]=A11*id; I[4]=A12*id; I[5]=A22*id;
}

// Build node i's initial blocks from inputs (closed forms).
__device__ __forceinline__ void build_node(int i,
        const float* __restrict__ C, const float* __restrict__ R,
        const float* __restrict__ IV, const float* __restrict__ ST,
        float D[6], float U[9], float B[3])
{
    float c0 = C[3*i], c1 = C[3*i+1], c2 = C[3*i+2];
    float rt = R[i];
    D[0]=c0*c0; D[1]=c0*c1; D[2]=c0*c2; D[3]=c1*c1; D[4]=c1*c2; D[5]=c2*c2;
    B[0]=c0*rt; B[1]=c1*rt; B[2]=c2*rt;
    if (i == 0) { D[0] += 1.0f; D[3] += 1.0f; B[0] += IV[0]; B[1] += IV[1]; }
    if (i < 99) {
        float h = ST[i], h2 = h*h;
        D[0] += 2.0f;      D[1] += h;                D[2] += 0.5f*h2;
        D[3] += h2+3.0f;   D[4] += h*(0.5f*h2+1.5f); D[5] += h2*(0.25f*h2+1.25f);
        U[0]=-2.0f;    U[1]=h;       U[2]=-0.5f*h2;
        U[3]=-h;       U[4]=-3.0f;   U[5]=1.5f*h;
        U[6]=-0.5f*h2; U[7]=-1.5f*h; U[8]=0.25f*h2;
    } else {
        #pragma unroll
        for (int k = 0; k < 9; ++k) U[k] = 0.0f;
    }
    if (i >= 1) {
        float g = ST[i-1], g2 = g*g;
        D[0] += 2.0f;      D[1] -= g;                D[2] += 0.5f*g2;
        D[3] += g2+3.0f;   D[4] -= g*(0.5f*g2+1.5f); D[5] += g2*(0.25f*g2+1.25f);
    }
}

// Left-neighbor elimination: D -= Uj^T Ij Uj ; B -= Uj^T (Ij Bj).
__device__ __forceinline__ void upd_left(float D[6], float B[3],
        const float Dj[6], const float Uj[9], const float Bj[3])
{
    float I[6]; inv3_sym(Dj, I);
    float T00=I[0]*Uj[0]+I[1]*Uj[3]+I[2]*Uj[6], T01=I[0]*Uj[1]+I[1]*Uj[4]+I[2]*Uj[7], T02=I[0]*Uj[2]+I[1]*Uj[5]+I[2]*Uj[8];
    float T10=I[1]*Uj[0]+I[3]*Uj[3]+I[4]*Uj[6], T11=I[1]*Uj[1]+I[3]*Uj[4]+I[4]*Uj[7], T12=I[1]*Uj[2]+I[3]*Uj[5]+I[4]*Uj[8];
    float T20=I[2]*Uj[0]+I[4]*Uj[3]+I[5]*Uj[6], T21=I[2]*Uj[1]+I[4]*Uj[4]+I[5]*Uj[7], T22=I[2]*Uj[2]+I[4]*Uj[5]+I[5]*Uj[8];
    D[0] -= Uj[0]*T00 + Uj[3]*T10 + Uj[6]*T20;
    D[1] -= Uj[0]*T01 + Uj[3]*T11 + Uj[6]*T21;
    D[2] -= Uj[0]*T02 + Uj[3]*T12 + Uj[6]*T22;
    D[3] -= Uj[1]*T01 + Uj[4]*T11 + Uj[7]*T21;
    D[4] -= Uj[1]*T02 + Uj[4]*T12 + Uj[7]*T22;
    D[5] -= Uj[2]*T02 + Uj[5]*T12 + Uj[8]*T22;
    float v0=I[0]*Bj[0]+I[1]*Bj[1]+I[2]*Bj[2];
    float v1=I[1]*Bj[0]+I[3]*Bj[1]+I[4]*Bj[2];
    float v2=I[2]*Bj[0]+I[4]*Bj[1]+I[5]*Bj[2];
    B[0] -= Uj[0]*v0 + Uj[3]*v1 + Uj[6]*v2;
    B[1] -= Uj[1]*v0 + Uj[4]*v1 + Uj[7]*v2;
    B[2] -= Uj[2]*v0 + Uj[5]*v1 + Uj[8]*v2;
}

// Right-neighbor elimination: P = U Ij; D -= P U^T; B -= P Bj; U' = -P Uj.
__device__ __forceinline__ void upd_right(float D[6], float U[9], float B[3],
        const float Dj[6], const float Uj[9], const float Bj[3], bool newU)
{
    float I[6]; inv3_sym(Dj, I);
    float P00=U[0]*I[0]+U[1]*I[1]+U[2]*I[2], P01=U[0]*I[1]+U[1]*I[3]+U[2]*I[4], P02=U[0]*I[2]+U[1]*I[4]+U[2]*I[5];
    float P10=U[3]*I[0]+U[4]*I[1]+U[5]*I[2], P11=U[3]*I[1]+U[4]*I[3]+U[5]*I[4], P12=U[3]*I[2]+U[4]*I[4]+U[5]*I[5];
    float P20=U[6]*I[0]+U[7]*I[1]+U[8]*I[2], P21=U[6]*I[1]+U[7]*I[3]+U[8]*I[4], P22=U[6]*I[2]+U[7]*I[4]+U[8]*I[5];
    D[0] -= P00*U[0] + P01*U[1] + P02*U[2];
    D[1] -= P00*U[3] + P01*U[4] + P02*U[5];
    D[2] -= P00*U[6] + P01*U[7] + P02*U[8];
    D[3] -= P10*U[3] + P11*U[4] + P12*U[5];
    D[4] -= P10*U[6] + P11*U[7] + P12*U[8];
    D[5] -= P20*U[6] + P21*U[7] + P22*U[8];
    B[0] -= P00*Bj[0] + P01*Bj[1] + P02*Bj[2];
    B[1] -= P10*Bj[0] + P11*Bj[1] + P12*Bj[2];
    B[2] -= P20*Bj[0] + P21*Bj[1] + P22*Bj[2];
    if (newU) {
        float N0 = -(P00*Uj[0] + P01*Uj[3] + P02*Uj[6]);
        float N1 = -(P00*Uj[1] + P01*Uj[4] + P02*Uj[7]);
        float N2 = -(P00*Uj[2] + P01*Uj[5] + P02*Uj[8]);
        float N3 = -(P10*Uj[0] + P11*Uj[3] + P12*Uj[6]);
        float N4 = -(P10*Uj[1] + P11*Uj[4] + P12*Uj[7]);
        float N5 = -(P10*Uj[2] + P11*Uj[5] + P12*Uj[8]);
        float N6 = -(P20*Uj[0] + P21*Uj[3] + P22*Uj[6]);
        float N7 = -(P20*Uj[1] + P21*Uj[4] + P22*Uj[7]);
        float N8 = -(P20*Uj[2] + P21*Uj[5] + P22*Uj[8]);
        U[0]=N0; U[1]=N1; U[2]=N2; U[3]=N3; U[4]=N4; U[5]=N5; U[6]=N6; U[7]=N7; U[8]=N8;
    }
}

__global__ __launch_bounds__(128)
void ode_pcr_v2_kernel(const float* __restrict__ coeffs,
                       const float* __restrict__ rhs,
                       const float* __restrict__ iv_rhs,
                       const float* __restrict__ steps,
                       float* __restrict__ out)
{
    // float4-packed, double-buffered node state (conflict-free).
    __shared__ float4 sA [2][NT];  // D0,D1,D2,D3
    __shared__ float4 sBv[2][NT];  // D4,D5,b0,b1
    __shared__ float4 sU0[2][NT];  // U0..U3
    __shared__ float4 sU1[2][NT];  // U4..U7
    __shared__ float4 sU2[2][NT];  // U8,b2,-,-

    const int sys = blockIdx.x;
    const int t   = threadIdx.x;

    const float* C  = coeffs + sys * 300;
    const float* R  = rhs    + sys * 100;
    const float* IV = iv_rhs + sys * 2;
    const float* ST = steps  + sys * 99;

    float st_local = 0.0f;
    float D[6], U[9], B[3];

    // ---------------- fused build + level 0 (s=1), all in registers ----------------
    if (t < NT) {
        if (t < 99) st_local = ST[t];
        build_node(t, C, R, IV, ST, D, U, B);
        if (t >= 1) {
            float Dl[6], Ul[9], Bl[3];
            build_node(t-1, C, R, IV, ST, Dl, Ul, Bl);
            upd_left(D, B, Dl, Ul, Bl);
        }
        if (t + 1 <= 99) {
            float Dr[6], Ur[9], Br[3];
            build_node(t+1, C, R, IV, ST, Dr, Ur, Br);
            upd_right(D, U, B, Dr, Ur, Br, (t + 2 <= 99));
        }
        // publish level-1 state to buffer 0
        sA [0][t] = make_float4(D[0],D[1],D[2],D[3]);
        sBv[0][t] = make_float4(D[4],D[5],B[0],B[1]);
        sU0[0][t] = make_float4(U[0],U[1],U[2],U[3]);
        sU1[0][t] = make_float4(U[4],U[5],U[6],U[7]);
        sU2[0][t] = make_float4(U[8],B[2],0.0f,0.0f);
    }
    __syncthreads();

    // ---------------- levels 1..6 (s = 2..64) via shared ----------------
    #pragma unroll
    for (int lvl = 1; lvl <= 6; ++lvl) {
        const int s   = 1 << lvl;
        const int cur = (lvl - 1) & 1;
        const int nxt = cur ^ 1;

        if (t < NT) {
            if (t >= s) {
                const int j = t - s;
                float4 a = sA[cur][j], bv = sBv[cur][j];
                float4 u0 = sU0[cur][j], u1 = sU1[cur][j], u2 = sU2[cur][j];
                float Dj[6] = {a.x,a.y,a.z,a.w,bv.x,bv.y};
                float Uj[9] = {u0.x,u0.y,u0.z,u0.w,u1.x,u1.y,u1.z,u1.w,u2.x};
                float Bj[3] = {bv.z,bv.w,u2.y};
                upd_left(D, B, Dj, Uj, Bj);
            }
            if (t + s <= 99) {
                const int j = t + s;
                float4 a = sA[cur][j], bv = sBv[cur][j];
                float4 u0 = sU0[cur][j], u1 = sU1[cur][j], u2 = sU2[cur][j];
                float Dj[6] = {a.x,a.y,a.z,a.w,bv.x,bv.y};
                float Uj[9] = {u0.x,u0.y,u0.z,u0.w,u1.x,u1.y,u1.z,u1.w,u2.x};
                float Bj[3] = {bv.z,bv.w,u2.y};
                upd_right(D, U, B, Dj, Uj, Bj, (t + 2*s <= 99));
            }
        }
        if (lvl < 6) {
            if (t < NT) {
                sA [nxt][t] = make_float4(D[0],D[1],D[2],D[3]);
                sBv[nxt][t] = make_float4(D[4],D[5],B[0],B[1]);
                sU0[nxt][t] = make_float4(U[0],U[1],U[2],U[3]);
                sU1[nxt][t] = make_float4(U[4],U[5],U[6],U[7]);
                sU2[nxt][t] = make_float4(U[8],B[2],0.0f,0.0f);
            }
            __syncthreads();
        }
    }

    // ---------------- diagonal solve + outputs ----------------
    if (t < NT) {
        float I[6]; inv3_sym(D, I);
        float x0 = I[0]*B[0] + I[1]*B[1] + I[2]*B[2];
        float x1 = I[1]*B[0] + I[3]*B[1] + I[4]*B[2];
        float x2 = I[2]*B[0] + I[4]*B[1] + I[5]*B[2];
        out[        sys*100 + t] = x0;
        out[25600 + sys*100 + t] = x1;
        out[51200 + sys*100 + t] = x2;
    }
    if (t == 0) out[76800 + sys] = 0.0f;
    if (t < 99) out[77056 + sys*99 + t] = st_local;
}

extern "C" void kernel_launch(void* const* d_in, const int* in_sizes, int n_in,
                              void* d_out, int out_size)
{
    (void)out_size;
    const float* coeffs = nullptr;
    const float* rhs    = nullptr;
    const float* iv_rhs = nullptr;
    const float* steps  = nullptr;
    for (int i = 0; i < n_in; ++i) {
        switch (in_sizes[i]) {
            case 76800: coeffs = (const float*)d_in[i]; break;
            case 25600: rhs    = (const float*)d_in[i]; break;
            case 512:   iv_rhs = (const float*)d_in[i]; break;
            case 25344: steps  = (const float*)d_in[i]; break;
            default: break;
        }
    }
    if (!coeffs && n_in > 0) coeffs = (const float*)d_in[0];
    if (!rhs    && n_in > 1) rhs    = (const float*)d_in[1];
    if (!iv_rhs && n_in > 2) iv_rhs = (const float*)d_in[2];
    if (!steps  && n_in > 3) steps  = (const float*)d_in[3];

    ode_pcr_v2_kernel<<<NSYS, 128>>>(coeffs, rhs, iv_rhs, steps, (float*)d_out);
}

// round 10
// speedup vs baseline: 65.4191x; 1.0257x over previous
#include <cuda_runtime.h>

// ODEINDLayer: 256 independent SPD block-tridiagonal systems (100 blocks of
// 3x3). Parallel cyclic reduction, pure fp32. Level 0 fused into registers;
// levels 1..6 via float4-packed double-buffered shared memory publishing
// (inv(D), U, b) per node — each node inverts its own diag ONCE pre-barrier,
// consumers never invert. One barrier per level.

#define NSYS 256
#define NT   100

__device__ __forceinline__ float frcp_nr(float x) {
    float r; asm("rcp.approx.f32 %0, %1;" : "=f"(r) : "f"(x));
    return r * (2.0f - x * r);
}

// Inverse of symmetric 3x3 (packed 00,01,02,11,12,22).
__device__ __forceinline__ void inv3_sym(const float M[6], float I[6]) {
    float A00 = M[3]*M[5] - M[4]*M[4];
    float A01 = M[2]*M[4] - M[1]*M[5];
    float A02 = M[1]*M[4] - M[2]*M[3];
    float A11 = M[0]*M[5] - M[2]*M[2];
    float A12 = M[1]*M[2] - M[0]*M[4];
    float A22 = M[0]*M[3] - M[1]*M[1];
    float id  = frcp_nr(M[0]*A00 + M[1]*A01 + M[2]*A02);
    I[0]=A00*id; I[1]=A01*id; I[2]=A02*id; I[3]=A11*id; I[4]=A12*id; I[5]=A22*id;
}

// Build node i's initial blocks from inputs (closed forms).
__device__ __forceinline__ void build_node(int i,
        const float* __restrict__ C, const float* __restrict__ R,
        const float* __restrict__ IV, const float* __restrict__ ST,
        float D[6], float U[9], float B[3])
{
    float c0 = C[3*i], c1 = C[3*i+1], c2 = C[3*i+2];
    float rt = R[i];
    D[0]=c0*c0; D[1]=c0*c1; D[2]=c0*c2; D[3]=c1*c1; D[4]=c1*c2; D[5]=c2*c2;
    B[0]=c0*rt; B[1]=c1*rt; B[2]=c2*rt;
    if (i == 0) { D[0] += 1.0f; D[3] += 1.0f; B[0] += IV[0]; B[1] += IV[1]; }
    if (i < 99) {
        float h = ST[i], h2 = h*h;
        D[0] += 2.0f;      D[1] += h;                D[2] += 0.5f*h2;
        D[3] += h2+3.0f;   D[4] += h*(0.5f*h2+1.5f); D[5] += h2*(0.25f*h2+1.25f);
        U[0]=-2.0f;    U[1]=h;       U[2]=-0.5f*h2;
        U[3]=-h;       U[4]=-3.0f;   U[5]=1.5f*h;
        U[6]=-0.5f*h2; U[7]=-1.5f*h; U[8]=0.25f*h2;
    } else {
        #pragma unroll
        for (int k = 0; k < 9; ++k) U[k] = 0.0f;
    }
    if (i >= 1) {
        float g = ST[i-1], g2 = g*g;
        D[0] += 2.0f;      D[1] -= g;                D[2] += 0.5f*g2;
        D[3] += g2+3.0f;   D[4] -= g*(0.5f*g2+1.5f); D[5] += g2*(0.25f*g2+1.25f);
    }
}

// Left elimination with PRE-INVERTED neighbor: D -= Uj^T (Ij Uj); B -= Uj^T (Ij Bj).
__device__ __forceinline__ void upd_left_inv(float D[6], float B[3],
        const float I[6], const float Uj[9], const float Bj[3])
{
    float T00=I[0]*Uj[0]+I[1]*Uj[3]+I[2]*Uj[6], T01=I[0]*Uj[1]+I[1]*Uj[4]+I[2]*Uj[7], T02=I[0]*Uj[2]+I[1]*Uj[5]+I[2]*Uj[8];
    float T10=I[1]*Uj[0]+I[3]*Uj[3]+I[4]*Uj[6], T11=I[1]*Uj[1]+I[3]*Uj[4]+I[4]*Uj[7], T12=I[1]*Uj[2]+I[3]*Uj[5]+I[4]*Uj[8];
    float T20=I[2]*Uj[0]+I[4]*Uj[3]+I[5]*Uj[6], T21=I[2]*Uj[1]+I[4]*Uj[4]+I[5]*Uj[7], T22=I[2]*Uj[2]+I[4]*Uj[5]+I[5]*Uj[8];
    D[0] -= Uj[0]*T00 + Uj[3]*T10 + Uj[6]*T20;
    D[1] -= Uj[0]*T01 + Uj[3]*T11 + Uj[6]*T21;
    D[2] -= Uj[0]*T02 + Uj[3]*T12 + Uj[6]*T22;
    D[3] -= Uj[1]*T01 + Uj[4]*T11 + Uj[7]*T21;
    D[4] -= Uj[1]*T02 + Uj[4]*T12 + Uj[7]*T22;
    D[5] -= Uj[2]*T02 + Uj[5]*T12 + Uj[8]*T22;
    float v0=I[0]*Bj[0]+I[1]*Bj[1]+I[2]*Bj[2];
    float v1=I[1]*Bj[0]+I[3]*Bj[1]+I[4]*Bj[2];
    float v2=I[2]*Bj[0]+I[4]*Bj[1]+I[5]*Bj[2];
    B[0] -= Uj[0]*v0 + Uj[3]*v1 + Uj[6]*v2;
    B[1] -= Uj[1]*v0 + Uj[4]*v1 + Uj[7]*v2;
    B[2] -= Uj[2]*v0 + Uj[5]*v1 + Uj[8]*v2;
}

// Right elimination with PRE-INVERTED neighbor: P=U Ij; D-=P U^T; B-=P Bj; U'=-P Uj.
__device__ __forceinline__ void upd_right_inv(float D[6], float U[9], float B[3],
        const float I[6], const float Uj[9], const float Bj[3], bool newU)
{
    float P00=U[0]*I[0]+U[1]*I[1]+U[2]*I[2], P01=U[0]*I[1]+U[1]*I[3]+U[2]*I[4], P02=U[0]*I[2]+U[1]*I[4]+U[2]*I[5];
    float P10=U[3]*I[0]+U[4]*I[1]+U[5]*I[2], P11=U[3]*I[1]+U[4]*I[3]+U[5]*I[4], P12=U[3]*I[2]+U[4]*I[4]+U[5]*I[5];
    float P20=U[6]*I[0]+U[7]*I[1]+U[8]*I[2], P21=U[6]*I[1]+U[7]*I[3]+U[8]*I[4], P22=U[6]*I[2]+U[7]*I[4]+U[8]*I[5];
    D[0] -= P00*U[0] + P01*U[1] + P02*U[2];
    D[1] -= P00*U[3] + P01*U[4] + P02*U[5];
    D[2] -= P00*U[6] + P01*U[7] + P02*U[8];
    D[3] -= P10*U[3] + P11*U[4] + P12*U[5];
    D[4] -= P10*U[6] + P11*U[7] + P12*U[8];
    D[5] -= P20*U[6] + P21*U[7] + P22*U[8];
    B[0] -= P00*Bj[0] + P01*Bj[1] + P02*Bj[2];
    B[1] -= P10*Bj[0] + P11*Bj[1] + P12*Bj[2];
    B[2] -= P20*Bj[0] + P21*Bj[1] + P22*Bj[2];
    if (newU) {
        float N0 = -(P00*Uj[0] + P01*Uj[3] + P02*Uj[6]);
        float N1 = -(P00*Uj[1] + P01*Uj[4] + P02*Uj[7]);
        float N2 = -(P00*Uj[2] + P01*Uj[5] + P02*Uj[8]);
        float N3 = -(P10*Uj[0] + P11*Uj[3] + P12*Uj[6]);
        float N4 = -(P10*Uj[1] + P11*Uj[4] + P12*Uj[7]);
        float N5 = -(P10*Uj[2] + P11*Uj[5] + P12*Uj[8]);
        float N6 = -(P20*Uj[0] + P21*Uj[3] + P22*Uj[6]);
        float N7 = -(P20*Uj[1] + P21*Uj[4] + P22*Uj[7]);
        float N8 = -(P20*Uj[2] + P21*Uj[5] + P22*Uj[8]);
        U[0]=N0; U[1]=N1; U[2]=N2; U[3]=N3; U[4]=N4; U[5]=N5; U[6]=N6; U[7]=N7; U[8]=N8;
    }
}

__global__ __launch_bounds__(128)
void ode_pcr_v3_kernel(const float* __restrict__ coeffs,
                       const float* __restrict__ rhs,
                       const float* __restrict__ iv_rhs,
                       const float* __restrict__ steps,
                       float* __restrict__ out)
{
    // Published per node & level: inv(D) [6], U [9], B [3] in 5 float4 slots.
    __shared__ float4 sA [2][NT];  // I0,I1,I2,I3
    __shared__ float4 sBv[2][NT];  // I4,I5,B0,B1
    __shared__ float4 sU0[2][NT];  // U0..U3
    __shared__ float4 sU1[2][NT];  // U4..U7
    __shared__ float4 sU2[2][NT];  // U8,B2,-,-

    const int sys = blockIdx.x;
    const int t   = threadIdx.x;

    const float* C  = coeffs + sys * 300;
    const float* R  = rhs    + sys * 100;
    const float* IV = iv_rhs + sys * 2;
    const float* ST = steps  + sys * 99;

    float st_local = 0.0f;
    float D[6], U[9], B[3];

    // ---------------- fused build + level 0 (s=1), all in registers ----------------
    if (t < NT) {
        if (t < 99) st_local = ST[t];
        build_node(t, C, R, IV, ST, D, U, B);
        if (t >= 1) {
            float Dl[6], Ul[9], Bl[3];
            build_node(t-1, C, R, IV, ST, Dl, Ul, Bl);
            float Il[6]; inv3_sym(Dl, Il);
            upd_left_inv(D, B, Il, Ul, Bl);
        }
        if (t + 1 <= 99) {
            float Dr[6], Ur[9], Br[3];
            build_node(t+1, C, R, IV, ST, Dr, Ur, Br);
            float Ir[6]; inv3_sym(Dr, Ir);
            upd_right_inv(D, U, B, Ir, Ur, Br, (t + 2 <= 99));
        }
        // publish level-1 state (own inverse computed once, pre-barrier)
        float I[6]; inv3_sym(D, I);
        sA [0][t] = make_float4(I[0],I[1],I[2],I[3]);
        sBv[0][t] = make_float4(I[4],I[5],B[0],B[1]);
        sU0[0][t] = make_float4(U[0],U[1],U[2],U[3]);
        sU1[0][t] = make_float4(U[4],U[5],U[6],U[7]);
        sU2[0][t] = make_float4(U[8],B[2],0.0f,0.0f);
    }
    __syncthreads();

    // ---------------- levels 1..6 (s = 2..64) via shared ----------------
    #pragma unroll
    for (int lvl = 1; lvl <= 6; ++lvl) {
        const int s   = 1 << lvl;
        const int cur = (lvl - 1) & 1;
        const int nxt = cur ^ 1;

        if (t < NT) {
            if (t >= s) {
                const int j = t - s;
                float4 a = sA[cur][j], bv = sBv[cur][j];
                float4 u0 = sU0[cur][j], u1 = sU1[cur][j], u2 = sU2[cur][j];
                float Ij[6] = {a.x,a.y,a.z,a.w,bv.x,bv.y};
                float Uj[9] = {u0.x,u0.y,u0.z,u0.w,u1.x,u1.y,u1.z,u1.w,u2.x};
                float Bj[3] = {bv.z,bv.w,u2.y};
                upd_left_inv(D, B, Ij, Uj, Bj);
            }
            if (t + s <= 99) {
                const int j = t + s;
                float4 a = sA[cur][j], bv = sBv[cur][j];
                float4 u0 = sU0[cur][j], u1 = sU1[cur][j], u2 = sU2[cur][j];
                float Ij[6] = {a.x,a.y,a.z,a.w,bv.x,bv.y};
                float Uj[9] = {u0.x,u0.y,u0.z,u0.w,u1.x,u1.y,u1.z,u1.w,u2.x};
                float Bj[3] = {bv.z,bv.w,u2.y};
                upd_right_inv(D, U, B, Ij, Uj, Bj, (t + 2*s <= 99));
            }
        }
        if (lvl < 6) {
            if (t < NT) {
                float I[6]; inv3_sym(D, I);
                sA [nxt][t] = make_float4(I[0],I[1],I[2],I[3]);
                sBv[nxt][t] = make_float4(I[4],I[5],B[0],B[1]);
                sU0[nxt][t] = make_float4(U[0],U[1],U[2],U[3]);
                sU1[nxt][t] = make_float4(U[4],U[5],U[6],U[7]);
                sU2[nxt][t] = make_float4(U[8],B[2],0.0f,0.0f);
            }
            __syncthreads();
        }
    }

    // ---------------- diagonal solve + outputs ----------------
    if (t < NT) {
        float I[6]; inv3_sym(D, I);
        float x0 = I[0]*B[0] + I[1]*B[1] + I[2]*B[2];
        float x1 = I[1]*B[0] + I[3]*B[1] + I[4]*B[2];
        float x2 = I[2]*B[0] + I[4]*B[1] + I[5]*B[2];
        out[        sys*100 + t] = x0;
        out[25600 + sys*100 + t] = x1;
        out[51200 + sys*100 + t] = x2;
    }
    if (t == 0) out[76800 + sys] = 0.0f;
    if (t < 99) out[77056 + sys*99 + t] = st_local;
}

extern "C" void kernel_launch(void* const* d_in, const int* in_sizes, int n_in,
                              void* d_out, int out_size)
{
    (void)out_size;
    const float* coeffs = nullptr;
    const float* rhs    = nullptr;
    const float* iv_rhs = nullptr;
    const float* steps  = nullptr;
    for (int i = 0; i < n_in; ++i) {
        switch (in_sizes[i]) {
            case 76800: coeffs = (const float*)d_in[i]; break;
            case 25600: rhs    = (const float*)d_in[i]; break;
            case 512:   iv_rhs = (const float*)d_in[i]; break;
            case 25344: steps  = (const float*)d_in[i]; break;
            default: break;
        }
    }
    if (!coeffs && n_in > 0) coeffs = (const float*)d_in[0];
    if (!rhs    && n_in > 1) rhs    = (const float*)d_in[1];
    if (!iv_rhs && n_in > 2) iv_rhs = (const float*)d_in[2];
    if (!steps  && n_in > 3) steps  = (const float*)d_in[3];

    ode_pcr_v3_kernel<<<NSYS, 128>>>(coeffs, rhs, iv_rhs, steps, (float*)d_out);
}